// round 11
// baseline (speedup 1.0000x reference)
#include <cuda_runtime.h>
#include <cuda_bf16.h>
#include <cstdint>
#include <stdint.h>
#include <math.h>

#define Ldim 128
#define Bdim 128
#define Vdim 300
#define Hdim 256
#define NEx  5
#define NCh  10      // 5 experts x 2 directions
#define G4   1024    // 4*H
#define H2   512     // 2*H
#define KPP  960     // proj K: 3 x 320 (hi, hi, lo sections)
#define KPA  1536    // attn K: 3 x 512

// ---------------- device scratch (no allocations allowed) ----------------
// g_PROJ gate-interleaved: [c][t][b][cg], cg = hd*4 + gate.
__device__ float g_PROJ[(size_t)NCh * Ldim * Bdim * G4];
__device__ float g_HS[(size_t)NEx * Bdim * Ldim * H2];     // [e][b][l][2H]
__device__ float g_s[(size_t)NEx * Bdim * Ldim];           // attention logits
__device__ float g_OUT[(size_t)NEx * Bdim * H2];           // pooled outputs

// bf16 split GEMM operands
__device__ __nv_bfloat16 g_pA[(size_t)16384 * KPP];        // proj A' [m][960]
__device__ __nv_bfloat16 g_pB[(size_t)10240 * KPP];        // proj B' [cg-ordered][960]
__device__ __nv_bfloat16 g_aA[(size_t)NEx * 16384 * 1024]; // attn A [e][m][hi512|lo512]
__device__ __nv_bfloat16 g_aB[(size_t)NEx * H2 * KPA];     // attn B' [e][o][whi|wlo|whi]

// recurrence W_hh as per-lane MMA fragments:
// g_wT[c][w][kt][nt][lane] = uint4 {bh0, bh1, bl0, bl1}  (10 MB total)
__device__ uint4 g_wT[(size_t)NCh * 8 * 16 * 16 * 32];

// ---------------- helpers ----------------
__device__ __forceinline__ float sigf(float x) { return 1.0f / (1.0f + __expf(-x)); }
__device__ __forceinline__ float tanh_fast(float x) {
    float cx = fminf(fmaxf(x, -15.0f), 15.0f);
    float e = __expf(2.0f * cx);
    return (e - 1.0f) / (e + 1.0f);
}
__device__ __forceinline__ void mma16816(float* c, const uint32_t* a, const uint32_t* b) {
    asm volatile(
        "mma.sync.aligned.m16n8k16.row.col.f32.bf16.bf16.f32 "
        "{%0,%1,%2,%3}, {%4,%5,%6,%7}, {%8,%9}, {%0,%1,%2,%3};"
        : "+f"(c[0]), "+f"(c[1]), "+f"(c[2]), "+f"(c[3])
        : "r"(a[0]), "r"(a[1]), "r"(a[2]), "r"(a[3]), "r"(b[0]), "r"(b[1]));
}
__device__ __forceinline__ uint32_t pack_bf2(__nv_bfloat16 a, __nv_bfloat16 b) {
    __nv_bfloat162 p; p.x = a; p.y = b;
    return *(uint32_t*)&p;
}
__device__ __forceinline__ uint32_t smem_u32(const void* p) {
    uint32_t a;
    asm("{ .reg .u64 t; cvta.to.shared.u64 t, %1; cvt.u32.u64 %0, t; }" : "=r"(a) : "l"(p));
    return a;
}

// ---------------- prep: proj operands (3-term split; B gate-interleaved) ----------------
__global__ __launch_bounds__(256) void prep_proj_kernel(
    const float* __restrict__ x,
    const float* __restrict__ wf, const float* __restrict__ wb)
{
    const int row = blockIdx.x;
    const int tid = threadIdx.x;
    if (row < 16384) {
        const float* src = x + (size_t)row * Vdim;
        __nv_bfloat16* dA = g_pA + (size_t)row * KPP;
        for (int col = tid; col < KPP; col += 256) {
            int s = col / 320, kk = col - s * 320;
            float v = (kk < Vdim) ? src[kk] : 0.0f;
            __nv_bfloat16 hi = __float2bfloat16(v);
            dA[col] = (s < 2) ? hi : __float2bfloat16(v - __bfloat162float(hi));
        }
    } else {
        const int n = row - 16384;                // n = c*1024 + cg
        const int c = n >> 10, e = c >> 1, d = c & 1;
        const int cg = n & 1023;
        const int gt = cg & 3, hd = cg >> 2;
        const float* src = (d ? wb : wf) + ((size_t)e * G4 + gt * 256 + hd) * Vdim;
        __nv_bfloat16* dB = g_pB + (size_t)n * KPP;
        for (int col = tid; col < KPP; col += 256) {
            int s = col / 320, kk = col - s * 320;
            float v = (kk < Vdim) ? src[kk] : 0.0f;
            __nv_bfloat16 hi = __float2bfloat16(v);
            dB[col] = (s == 1) ? __float2bfloat16(v - __bfloat162float(hi)) : hi;
        }
    }
}

// ---------------- prep: W_hh fragment layout ----------------
__global__ __launch_bounds__(256) void prep_wT_kernel(
    const float* __restrict__ whf, const float* __restrict__ whb)
{
    const int idx = blockIdx.x * 256 + threadIdx.x;   // 655360 total
    const int lane = idx & 31;
    const int nt = (idx >> 5) & 15;
    const int kt = (idx >> 9) & 15;
    const int w = (idx >> 13) & 7;
    const int c = idx >> 16;
    const int e = c >> 1, d = c & 1;
    const int cg = w * 128 + nt * 8 + (lane >> 2);
    const int gate = cg & 3, hd = cg >> 2;
    const float* src = (d ? whb : whf) + ((size_t)e * G4 + gate * 256 + hd) * Hdim;
    const int k0 = kt * 16 + (lane & 3) * 2;
    float v00 = src[k0],     v01 = src[k0 + 1];
    float v10 = src[k0 + 8], v11 = src[k0 + 9];
    __nv_bfloat16 h00 = __float2bfloat16(v00), h01 = __float2bfloat16(v01);
    __nv_bfloat16 h10 = __float2bfloat16(v10), h11 = __float2bfloat16(v11);
    uint4 o;
    o.x = pack_bf2(h00, h01);
    o.y = pack_bf2(h10, h11);
    o.z = pack_bf2(__float2bfloat16(v00 - __bfloat162float(h00)),
                   __float2bfloat16(v01 - __bfloat162float(h01)));
    o.w = pack_bf2(__float2bfloat16(v10 - __bfloat162float(h10)),
                   __float2bfloat16(v11 - __bfloat162float(h11)));
    g_wT[idx] = o;
}

// ---------------- prep: attn B' (whi | wlo | whi) ----------------
__global__ __launch_bounds__(256) void prep_attnB_kernel(const float* __restrict__ attW)
{
    const int r = blockIdx.x;                 // e*512 + o
    const int tid = threadIdx.x;
    const float* src = attW + (size_t)r * H2;
    __nv_bfloat16* dB = g_aB + (size_t)r * KPA;
    for (int col = tid; col < KPA; col += 256) {
        int s = col >> 9, kk = col & 511;
        float v = src[kk];
        __nv_bfloat16 hi = __float2bfloat16(v);
        dB[col] = (s == 1) ? __float2bfloat16(v - __bfloat162float(hi)) : hi;
    }
}

// ---------------- prep: attn A (hi | lo of g_HS) ----------------
__global__ __launch_bounds__(256) void prep_attnA_kernel()
{
    const int r = blockIdx.x;                 // e*16384 + m
    const int tid = threadIdx.x;
    const float* src = g_HS + (size_t)r * H2;
    __nv_bfloat16* dA = g_aA + (size_t)r * 1024;
    for (int col = tid; col < 1024; col += 256) {
        int kk = col & 511;
        float v = src[kk];
        __nv_bfloat16 hi = __float2bfloat16(v);
        dA[col] = (col < 512) ? hi : __float2bfloat16(v - __bfloat162float(hi));
    }
}

// ---------------- proj GEMM (mma.sync bf16) ----------------
__global__ __launch_bounds__(256) void proj_mma_kernel(
    const float* __restrict__ bf, const float* __restrict__ bb)
{
    __shared__ __align__(16) uint32_t As[128][36];
    __shared__ __align__(16) uint32_t Bs[128][36];
    __shared__ float biasS[128];

    const int tid = threadIdx.x;
    const int warp = tid >> 5, lane = tid & 31;
    const int g = lane >> 2, tg = lane & 3;
    const int warp_m = (warp >> 2) * 64;
    const int warp_n = (warp & 3) * 32;

    const int n0 = blockIdx.x * 128;
    const int m0 = blockIdx.y * 128;
    const int b_i = blockIdx.y;
    const int c = n0 >> 10, e = c >> 1, d = c & 1;
    const int g0 = n0 & 1023;

    {
        const float* bias = (d ? bb : bf) + (size_t)e * G4;
        if (tid < 128) {
            int cg = g0 + tid;
            biasS[tid] = bias[(cg & 3) * 256 + (cg >> 2)];
        }
    }

    float acc[4][4][4];
#pragma unroll
    for (int m = 0; m < 4; m++)
#pragma unroll
        for (int n = 0; n < 4; n++)
#pragma unroll
            for (int q = 0; q < 4; q++) acc[m][n][q] = 0.0f;

    const uint4* Ag = (const uint4*)g_pA;
    const uint4* Bg = (const uint4*)g_pB;

    for (int kc = 0; kc < 15; kc++) {
#pragma unroll
        for (int q = 0; q < 4; q++) {
            int idx = tid + q * 256;
            int r = idx >> 3, ju = idx & 7;
            *(uint4*)&As[r][ju * 4] = Ag[(size_t)(m0 + r) * 120 + kc * 8 + ju];
            *(uint4*)&Bs[r][ju * 4] = Bg[(size_t)(n0 + r) * 120 + kc * 8 + ju];
        }
        __syncthreads();
#pragma unroll
        for (int ks = 0; ks < 4; ks++) {
            uint32_t af[4][4], bfr[4][2];
#pragma unroll
            for (int m = 0; m < 4; m++) {
                int r0 = warp_m + m * 16 + g;
                af[m][0] = As[r0][ks * 8 + tg];
                af[m][1] = As[r0 + 8][ks * 8 + tg];
                af[m][2] = As[r0][ks * 8 + tg + 4];
                af[m][3] = As[r0 + 8][ks * 8 + tg + 4];
            }
#pragma unroll
            for (int n = 0; n < 4; n++) {
                int rn = warp_n + n * 8 + g;
                bfr[n][0] = Bs[rn][ks * 8 + tg];
                bfr[n][1] = Bs[rn][ks * 8 + tg + 4];
            }
#pragma unroll
            for (int m = 0; m < 4; m++)
#pragma unroll
                for (int n = 0; n < 4; n++) mma16816(acc[m][n], af[m], bfr[n]);
        }
        __syncthreads();
    }

#pragma unroll
    for (int m = 0; m < 4; m++) {
        int l0 = warp_m + m * 16 + g;
        int l1 = l0 + 8;
        int t0 = d ? (Ldim - 1 - l0) : l0;
        int t1 = d ? (Ldim - 1 - l1) : l1;
        float* base0 = g_PROJ + (((size_t)c * Ldim + t0) * Bdim + b_i) * G4 + g0 + warp_n;
        float* base1 = g_PROJ + (((size_t)c * Ldim + t1) * Bdim + b_i) * G4 + g0 + warp_n;
#pragma unroll
        for (int n = 0; n < 4; n++) {
            int cc = n * 8 + 2 * tg;
            float2 v0 = { acc[m][n][0] + biasS[warp_n + cc],
                          acc[m][n][1] + biasS[warp_n + cc + 1] };
            float2 v1 = { acc[m][n][2] + biasS[warp_n + cc],
                          acc[m][n][3] + biasS[warp_n + cc + 1] };
            *(float2*)(base0 + cc) = v0;
            *(float2*)(base1 + cc) = v1;
        }
    }
}

// ---------------- LSTM recurrence: batch-partitioned + cp.async W staging ----------------
// grid 80 = 10 chains x 8 batch-slices of 16 rows. Each CTA computes ALL 1024
// gates for its rows; h stays CTA-private in SMEM. W_hh (t-invariant) is staged
// per-kt into SMEM with a double-buffered cp.async pipeline -> L2 latency hidden.
#define LSTM_SMEM (2 * 4096 * 16 + 2 * 16 * 132 * 4)   // 131072 + 16896 = 147,968 B

__global__ __launch_bounds__(256, 1) void lstm_batch_kernel()
{
    extern __shared__ __align__(16) uint4 smw[];        // [2][4096] staged W
    uint32_t* Hhi = (uint32_t*)(smw + 8192);            // [16][132]
    uint32_t* Hlo = Hhi + 16 * 132;

    const int bid = blockIdx.x;
    const int c = bid >> 3, s = bid & 7;
    const int b0 = s * 16;
    const int e = c >> 1, d = c & 1;
    const int tid = threadIdx.x;
    const int warp = tid >> 5, lane = tid & 31;
    const int g = lane >> 2, tg = lane & 3;
    const bool evenp = (tg & 1) == 0;

    const uint4* Wc = g_wT + (size_t)c * 65536;         // chain base (8*256*32)
    const uint32_t swbase = smem_u32(smw);

#define STAGE(KT, BUF) do {                                                   \
    uint32_t dstb = swbase + (BUF) * 65536;                                   \
    const uint4* srcb = Wc + (size_t)(KT) * 512;                              \
    _Pragma("unroll")                                                         \
    for (int q = 0; q < 16; q++) {                                            \
        int idx = tid + q * 256;                                              \
        const uint4* src = srcb + (idx >> 9) * 8192 + (idx & 511);            \
        asm volatile("cp.async.cg.shared.global [%0], [%1], 16;"              \
                     :: "r"(dstb + idx * 16), "l"(src));                      \
    }                                                                         \
    asm volatile("cp.async.commit_group;" ::: "memory");                      \
} while (0)

    float cst[16];
#pragma unroll
    for (int i = 0; i < 16; i++) cst[i] = 0.0f;

    // prologue: stage kt=0 (used by t=1)
    STAGE(0, 0);

    for (int t = 0; t < Ldim; t++) {
        float acc[16][4];
#pragma unroll
        for (int nt = 0; nt < 16; nt++)
#pragma unroll
            for (int q = 0; q < 4; q++) acc[nt][q] = 0.0f;

        if (t > 0) {
            for (int kt = 0; kt < 16; kt++) {
                if (kt < 15) {
                    STAGE(kt + 1, (kt + 1) & 1);
                    asm volatile("cp.async.wait_group 1;" ::: "memory");
                } else {
                    asm volatile("cp.async.wait_group 0;" ::: "memory");
                }
                __syncthreads();   // staged buf[kt&1] visible to all warps

                uint32_t ah[4], al[4];
                ah[0] = Hhi[g * 132 + kt * 8 + tg];
                ah[1] = Hhi[(g + 8) * 132 + kt * 8 + tg];
                ah[2] = Hhi[g * 132 + kt * 8 + tg + 4];
                ah[3] = Hhi[(g + 8) * 132 + kt * 8 + tg + 4];
                al[0] = Hlo[g * 132 + kt * 8 + tg];
                al[1] = Hlo[(g + 8) * 132 + kt * 8 + tg];
                al[2] = Hlo[g * 132 + kt * 8 + tg + 4];
                al[3] = Hlo[(g + 8) * 132 + kt * 8 + tg + 4];

                const uint4* Wst = smw + (kt & 1) * 4096 + warp * 512 + lane;
#pragma unroll
                for (int nt = 0; nt < 16; nt++) {
                    uint4 wv = Wst[nt * 32];
                    uint32_t bh[2] = { wv.x, wv.y };
                    uint32_t bl[2] = { wv.z, wv.w };
                    mma16816(acc[nt], ah, bh);
                    mma16816(acc[nt], ah, bl);
                    mma16816(acc[nt], al, bh);
                }
                __syncthreads();   // reads done before this buffer is re-staged
            }
            if (t < Ldim - 1) STAGE(0, 0);   // next step's kt=0, overlaps pointwise
        }

        // ---- pointwise: gate exchange (xor 1), LSTM cell, h -> SMEM + g_HS ----
        const int lo_t = d ? (Ldim - 1 - t) : t;
        const float* projb = g_PROJ + (((size_t)c * Ldim + t) * Bdim + b0) * G4;
        const int row = g + (evenp ? 0 : 8);
#pragma unroll
        for (int nt = 0; nt < 16; nt++) {
            float a0 = acc[nt][0], a1 = acc[nt][1];
            float a2 = acc[nt][2], a3 = acc[nt][3];
            float t0 = __shfl_xor_sync(0xFFFFFFFFu, a0, 1);
            float t1 = __shfl_xor_sync(0xFFFFFFFFu, a1, 1);
            float t2 = __shfl_xor_sync(0xFFFFFFFFu, a2, 1);
            float t3 = __shfl_xor_sync(0xFFFFFFFFu, a3, 1);
            int hd = warp * 32 + nt * 2 + (tg >> 1);
            float4 pj = *(const float4*)(projb + (size_t)row * G4 + hd * 4);
            float gi = (evenp ? a0 : t2) + pj.x;
            float gf = (evenp ? a1 : t3) + pj.y;
            float gg = (evenp ? t0 : a2) + pj.z;
            float go = (evenp ? t1 : a3) + pj.w;
            float cn = sigf(gf) * cst[nt] + sigf(gi) * tanh_fast(gg);
            cst[nt] = cn;
            float h = sigf(go) * tanh_fast(cn);
            g_HS[(((size_t)e * Bdim + (b0 + row)) * Ldim + lo_t) * H2 + d * Hdim + hd] = h;
            float hB = __shfl_xor_sync(0xFFFFFFFFu, h, 2);
            if ((tg >> 1) == 0) {
                __nv_bfloat16 hhA = __float2bfloat16(h);
                __nv_bfloat16 hhB = __float2bfloat16(hB);
                Hhi[row * 132 + warp * 16 + nt] = pack_bf2(hhA, hhB);
                Hlo[row * 132 + warp * 16 + nt] = pack_bf2(
                    __float2bfloat16(h - __bfloat162float(hhA)),
                    __float2bfloat16(hB - __bfloat162float(hhB)));
            }
        }
        __syncthreads();   // h visible before next step's A-frag reads
    }
#undef STAGE
}

// ---------------- attention logits GEMM (mma.sync bf16) ----------------
__global__ __launch_bounds__(256) void attn_mma_kernel(
    const float* __restrict__ attb, const float* __restrict__ attv)
{
    __shared__ __align__(16) uint32_t As[128][36];
    __shared__ __align__(16) uint32_t Bs[128][36];
    __shared__ float red[128][17];

    const int tid = threadIdx.x;
    const int warp = tid >> 5, lane = tid & 31;
    const int g = lane >> 2, tg = lane & 3;
    const int warp_m = (warp >> 2) * 64;
    const int warp_n = (warp & 3) * 32;

    const int m0 = blockIdx.x * 128;
    const int e = blockIdx.y;

    const uint4* Ag = (const uint4*)g_aA;
    const uint4* Bg = (const uint4*)g_aB;
    const float* abp = attb + (size_t)e * H2;
    const float* avp = attv + (size_t)e * H2;

    float part[4][2];
#pragma unroll
    for (int m = 0; m < 4; m++) { part[m][0] = 0.0f; part[m][1] = 0.0f; }

    for (int nc = 0; nc < 4; nc++) {
        const int n0 = nc * 128;
        float acc[4][4][4];
#pragma unroll
        for (int m = 0; m < 4; m++)
#pragma unroll
            for (int n = 0; n < 4; n++)
#pragma unroll
                for (int q = 0; q < 4; q++) acc[m][n][q] = 0.0f;

        for (int kc = 0; kc < 24; kc++) {
            const int pp = kc >> 3, within = kc & 7;
            const int au4 = (pp == 2 ? 64 : 0) + within * 8;
            const int bu4 = kc * 8;
#pragma unroll
            for (int q = 0; q < 4; q++) {
                int idx = tid + q * 256;
                int r = idx >> 3, ju = idx & 7;
                *(uint4*)&As[r][ju * 4] =
                    Ag[((size_t)e * 16384 + m0 + r) * 128 + au4 + ju];
                *(uint4*)&Bs[r][ju * 4] =
                    Bg[((size_t)e * H2 + n0 + r) * 192 + bu4 + ju];
            }
            __syncthreads();
#pragma unroll
            for (int ks = 0; ks < 4; ks++) {
                uint32_t af[4][4], bfr[4][2];
#pragma unroll
                for (int m = 0; m < 4; m++) {
                    int r0 = warp_m + m * 16 + g;
                    af[m][0] = As[r0][ks * 8 + tg];
                    af[m][1] = As[r0 + 8][ks * 8 + tg];
                    af[m][2] = As[r0][ks * 8 + tg + 4];
                    af[m][3] = As[r0 + 8][ks * 8 + tg + 4];
                }
#pragma unroll
                for (int n = 0; n < 4; n++) {
                    int rn = warp_n + n * 8 + g;
                    bfr[n][0] = Bs[rn][ks * 8 + tg];
                    bfr[n][1] = Bs[rn][ks * 8 + tg + 4];
                }
#pragma unroll
                for (int m = 0; m < 4; m++)
#pragma unroll
                    for (int n = 0; n < 4; n++) mma16816(acc[m][n], af[m], bfr[n]);
            }
            __syncthreads();
        }

#pragma unroll
        for (int n = 0; n < 4; n++) {
            int o = n0 + warp_n + n * 8 + 2 * tg;
            float ab0 = abp[o], ab1 = abp[o + 1];
            float av0 = avp[o], av1 = avp[o + 1];
#pragma unroll
            for (int m = 0; m < 4; m++) {
                part[m][0] += tanh_fast(acc[m][n][0] + ab0) * av0
                            + tanh_fast(acc[m][n][1] + ab1) * av1;
                part[m][1] += tanh_fast(acc[m][n][2] + ab0) * av0
                            + tanh_fast(acc[m][n][3] + ab1) * av1;
            }
        }
    }

#pragma unroll
    for (int m = 0; m < 4; m++) {
        int r0 = warp_m + m * 16 + g;
        red[r0][(warp & 3) * 4 + tg] = part[m][0];
        red[r0 + 8][(warp & 3) * 4 + tg] = part[m][1];
    }
    __syncthreads();
    if (tid < 128) {
        float ss = 0.0f;
#pragma unroll
        for (int q = 0; q < 16; q++) ss += red[tid][q];
        g_s[(size_t)e * Bdim * Ldim + m0 + tid] = ss;
    }
}

// ---------------- softmax over L + weighted pooling ----------------
__global__ __launch_bounds__(128) void softmax_pool_kernel()
{
    const int e = blockIdx.y, b = blockIdx.x;
    __shared__ float wts[Ldim];
    __shared__ float red[128];
    const int tid = threadIdx.x;

    float v = g_s[((size_t)e * Bdim + b) * Ldim + tid];
    red[tid] = v; __syncthreads();
    for (int st = 64; st > 0; st >>= 1) {
        if (tid < st) red[tid] = fmaxf(red[tid], red[tid + st]);
        __syncthreads();
    }
    float mx = red[0]; __syncthreads();
    float ev = expf(v - mx);
    red[tid] = ev; __syncthreads();
    for (int st = 64; st > 0; st >>= 1) {
        if (tid < st) red[tid] += red[tid + st];
        __syncthreads();
    }
    float inv = 1.0f / red[0];
    wts[tid] = ev * inv;
    __syncthreads();

    const float* hrow = g_HS + ((size_t)e * Bdim + b) * Ldim * H2;
    float accv[4] = {0.f, 0.f, 0.f, 0.f};
    for (int l = 0; l < Ldim; l++) {
        float a = wts[l];
        const float* hp = hrow + (size_t)l * H2;
#pragma unroll
        for (int j = 0; j < 4; j++) accv[j] += a * hp[tid + j * 128];
    }
    float* op = g_OUT + ((size_t)e * Bdim + b) * H2;
#pragma unroll
    for (int j = 0; j < 4; j++) op[tid + j * 128] = accv[j];
}

// ---------------- output copy + final FC ----------------
__global__ void copy_out_kernel(float* __restrict__ out)
{
    int i = blockIdx.x * blockDim.x + threadIdx.x;
    if (i < NEx * Bdim * H2) out[256 + i] = g_OUT[i];
}

__global__ __launch_bounds__(128) void final_kernel(
    const int* __restrict__ z, const float* __restrict__ fcW,
    const float* __restrict__ fcb, float* __restrict__ out)
{
    const int b = blockIdx.x;
    const int tid = threadIdx.x;
    const int zi = z[b];
    const float* sel = g_OUT + ((size_t)(1 + zi) * Bdim + b) * H2;
    const float* gen = g_OUT + (size_t)b * H2;
    __shared__ float red0[128], red1[128];
    float a0 = 0.f, a1 = 0.f;
    for (int dd = tid; dd < 1024; dd += 128) {
        float cv = (dd < 512) ? sel[dd] : gen[dd - 512];
        a0 += cv * fcW[dd];
        a1 += cv * fcW[1024 + dd];
    }
    red0[tid] = a0; red1[tid] = a1; __syncthreads();
    for (int st = 64; st > 0; st >>= 1) {
        if (tid < st) { red0[tid] += red0[tid + st]; red1[tid] += red1[tid + st]; }
        __syncthreads();
    }
    if (tid == 0) {
        out[b * 2 + 0] = red0[0] + fcb[0];
        out[b * 2 + 1] = red1[0] + fcb[1];
    }
}

// ---------------- launch ----------------
extern "C" void kernel_launch(void* const* d_in, const int* in_sizes, int n_in,
                              void* d_out, int out_size)
{
    (void)in_sizes; (void)n_in; (void)out_size;
    const float* x     = (const float*)d_in[0];
    const int*   z     = (const int*)  d_in[1];
    const float* wih_f = (const float*)d_in[2];
    const float* whh_f = (const float*)d_in[3];
    const float* b_f   = (const float*)d_in[4];
    const float* wih_b = (const float*)d_in[5];
    const float* whh_b = (const float*)d_in[6];
    const float* b_b   = (const float*)d_in[7];
    const float* attW  = (const float*)d_in[8];
    const float* attb  = (const float*)d_in[9];
    const float* attv  = (const float*)d_in[10];
    const float* fcW   = (const float*)d_in[11];
    const float* fcb   = (const float*)d_in[12];
    float* out = (float*)d_out;

    cudaFuncSetAttribute(lstm_batch_kernel,
                         cudaFuncAttributeMaxDynamicSharedMemorySize, LSTM_SMEM);

    prep_proj_kernel<<<16384 + 10240, 256>>>(x, wih_f, wih_b);
    prep_wT_kernel<<<2560, 256>>>(whh_f, whh_b);
    prep_attnB_kernel<<<NEx * H2, 256>>>(attW);
    proj_mma_kernel<<<dim3(80, 128), 256>>>(b_f, b_b);
    lstm_batch_kernel<<<80, 256, LSTM_SMEM>>>();
    prep_attnA_kernel<<<NEx * 16384, 256>>>();
    attn_mma_kernel<<<dim3(128, 5), 256>>>(attb, attv);
    softmax_pool_kernel<<<dim3(128, 5), 128>>>();
    copy_out_kernel<<<(NEx * Bdim * H2 + 255) / 256, 256>>>(out);
    final_kernel<<<128, 128>>>(z, fcW, fcb, out);
}

// round 12
// speedup vs baseline: 1.3764x; 1.3764x over previous
#include <cuda_runtime.h>
#include <cuda_bf16.h>
#include <cstdint>
#include <stdint.h>
#include <math.h>

#define Ldim 128
#define Bdim 128
#define Vdim 300
#define Hdim 256
#define NEx  5
#define NCh  10      // 5 experts x 2 directions
#define G4   1024    // 4*H
#define H2   512     // 2*H
#define KPP  960     // proj K: 3 x 320 (hi, hi, lo sections)
#define KPA  1536    // attn K: 3 x 512

// ---------------- device scratch (no allocations allowed) ----------------
// g_PROJ gate-interleaved: [c][t][b][cg], cg = hd*4 + gate.
__device__ float g_PROJ[(size_t)NCh * Ldim * Bdim * G4];
__device__ float g_HS[(size_t)NEx * Bdim * Ldim * H2];     // [e][b][l][2H]
__device__ float g_s[(size_t)NEx * Bdim * Ldim];           // attention logits
__device__ float g_OUT[(size_t)NEx * Bdim * H2];           // pooled outputs

// bf16 split GEMM operands
__device__ __nv_bfloat16 g_pA[(size_t)16384 * KPP];        // proj A' [m][960]
__device__ __nv_bfloat16 g_pB[(size_t)10240 * KPP];        // proj B' [cg-ordered][960]
__device__ __nv_bfloat16 g_aA[(size_t)NEx * 16384 * 1024]; // attn A [e][m][hi512|lo512]
__device__ __nv_bfloat16 g_aB[(size_t)NEx * H2 * KPA];     // attn B' [e][o][whi|wlo|whi]

// recurrence W_hh as per-lane MMA fragments:
// g_wT[c][w][kt][nt][lane] = uint4 {bh0, bh1, bl0, bl1}  (10 MB total)
__device__ uint4 g_wT[(size_t)NCh * 8 * 16 * 16 * 32];

// ---------------- helpers ----------------
__device__ __forceinline__ float sigf(float x) { return 1.0f / (1.0f + __expf(-x)); }
__device__ __forceinline__ float tanh_fast(float x) {
    float cx = fminf(fmaxf(x, -15.0f), 15.0f);
    float e = __expf(2.0f * cx);
    return (e - 1.0f) / (e + 1.0f);
}
__device__ __forceinline__ void mma16816(float* c, const uint32_t* a, const uint32_t* b) {
    asm volatile(
        "mma.sync.aligned.m16n8k16.row.col.f32.bf16.bf16.f32 "
        "{%0,%1,%2,%3}, {%4,%5,%6,%7}, {%8,%9}, {%0,%1,%2,%3};"
        : "+f"(c[0]), "+f"(c[1]), "+f"(c[2]), "+f"(c[3])
        : "r"(a[0]), "r"(a[1]), "r"(a[2]), "r"(a[3]), "r"(b[0]), "r"(b[1]));
}
__device__ __forceinline__ uint32_t pack_bf2(__nv_bfloat16 a, __nv_bfloat16 b) {
    __nv_bfloat162 p; p.x = a; p.y = b;
    return *(uint32_t*)&p;
}

// ---------------- prep: proj operands (3-term split; B gate-interleaved) ----------------
__global__ __launch_bounds__(256) void prep_proj_kernel(
    const float* __restrict__ x,
    const float* __restrict__ wf, const float* __restrict__ wb)
{
    const int row = blockIdx.x;
    const int tid = threadIdx.x;
    if (row < 16384) {
        const float* src = x + (size_t)row * Vdim;
        __nv_bfloat16* dA = g_pA + (size_t)row * KPP;
        for (int col = tid; col < KPP; col += 256) {
            int s = col / 320, kk = col - s * 320;
            float v = (kk < Vdim) ? src[kk] : 0.0f;
            __nv_bfloat16 hi = __float2bfloat16(v);
            dA[col] = (s < 2) ? hi : __float2bfloat16(v - __bfloat162float(hi));
        }
    } else {
        const int n = row - 16384;                // n = c*1024 + cg
        const int c = n >> 10, e = c >> 1, d = c & 1;
        const int cg = n & 1023;
        const int gt = cg & 3, hd = cg >> 2;
        const float* src = (d ? wb : wf) + ((size_t)e * G4 + gt * 256 + hd) * Vdim;
        __nv_bfloat16* dB = g_pB + (size_t)n * KPP;
        for (int col = tid; col < KPP; col += 256) {
            int s = col / 320, kk = col - s * 320;
            float v = (kk < Vdim) ? src[kk] : 0.0f;
            __nv_bfloat16 hi = __float2bfloat16(v);
            dB[col] = (s == 1) ? __float2bfloat16(v - __bfloat162float(hi)) : hi;
        }
    }
}

// ---------------- prep: W_hh fragment layout ----------------
__global__ __launch_bounds__(256) void prep_wT_kernel(
    const float* __restrict__ whf, const float* __restrict__ whb)
{
    const int idx = blockIdx.x * 256 + threadIdx.x;   // 655360 total
    const int lane = idx & 31;
    const int nt = (idx >> 5) & 15;
    const int kt = (idx >> 9) & 15;
    const int w = (idx >> 13) & 7;
    const int c = idx >> 16;
    const int e = c >> 1, d = c & 1;
    const int cg = w * 128 + nt * 8 + (lane >> 2);
    const int gate = cg & 3, hd = cg >> 2;
    const float* src = (d ? whb : whf) + ((size_t)e * G4 + gate * 256 + hd) * Hdim;
    const int k0 = kt * 16 + (lane & 3) * 2;
    float v00 = src[k0],     v01 = src[k0 + 1];
    float v10 = src[k0 + 8], v11 = src[k0 + 9];
    __nv_bfloat16 h00 = __float2bfloat16(v00), h01 = __float2bfloat16(v01);
    __nv_bfloat16 h10 = __float2bfloat16(v10), h11 = __float2bfloat16(v11);
    uint4 o;
    o.x = pack_bf2(h00, h01);
    o.y = pack_bf2(h10, h11);
    o.z = pack_bf2(__float2bfloat16(v00 - __bfloat162float(h00)),
                   __float2bfloat16(v01 - __bfloat162float(h01)));
    o.w = pack_bf2(__float2bfloat16(v10 - __bfloat162float(h10)),
                   __float2bfloat16(v11 - __bfloat162float(h11)));
    g_wT[idx] = o;
}

// ---------------- prep: attn B' (whi | wlo | whi) ----------------
__global__ __launch_bounds__(256) void prep_attnB_kernel(const float* __restrict__ attW)
{
    const int r = blockIdx.x;                 // e*512 + o
    const int tid = threadIdx.x;
    const float* src = attW + (size_t)r * H2;
    __nv_bfloat16* dB = g_aB + (size_t)r * KPA;
    for (int col = tid; col < KPA; col += 256) {
        int s = col >> 9, kk = col & 511;
        float v = src[kk];
        __nv_bfloat16 hi = __float2bfloat16(v);
        dB[col] = (s == 1) ? __float2bfloat16(v - __bfloat162float(hi)) : hi;
    }
}

// ---------------- prep: attn A (hi | lo of g_HS) ----------------
__global__ __launch_bounds__(256) void prep_attnA_kernel()
{
    const int r = blockIdx.x;                 // e*16384 + m
    const int tid = threadIdx.x;
    const float* src = g_HS + (size_t)r * H2;
    __nv_bfloat16* dA = g_aA + (size_t)r * 1024;
    for (int col = tid; col < 1024; col += 256) {
        int kk = col & 511;
        float v = src[kk];
        __nv_bfloat16 hi = __float2bfloat16(v);
        dA[col] = (col < 512) ? hi : __float2bfloat16(v - __bfloat162float(hi));
    }
}

// ---------------- proj GEMM (mma.sync bf16) ----------------
__global__ __launch_bounds__(256) void proj_mma_kernel(
    const float* __restrict__ bf, const float* __restrict__ bb)
{
    __shared__ __align__(16) uint32_t As[128][36];
    __shared__ __align__(16) uint32_t Bs[128][36];
    __shared__ float biasS[128];

    const int tid = threadIdx.x;
    const int warp = tid >> 5, lane = tid & 31;
    const int g = lane >> 2, tg = lane & 3;
    const int warp_m = (warp >> 2) * 64;
    const int warp_n = (warp & 3) * 32;

    const int n0 = blockIdx.x * 128;
    const int m0 = blockIdx.y * 128;
    const int b_i = blockIdx.y;
    const int c = n0 >> 10, e = c >> 1, d = c & 1;
    const int g0 = n0 & 1023;

    {
        const float* bias = (d ? bb : bf) + (size_t)e * G4;
        if (tid < 128) {
            int cg = g0 + tid;
            biasS[tid] = bias[(cg & 3) * 256 + (cg >> 2)];
        }
    }

    float acc[4][4][4];
#pragma unroll
    for (int m = 0; m < 4; m++)
#pragma unroll
        for (int n = 0; n < 4; n++)
#pragma unroll
            for (int q = 0; q < 4; q++) acc[m][n][q] = 0.0f;

    const uint4* Ag = (const uint4*)g_pA;
    const uint4* Bg = (const uint4*)g_pB;

    for (int kc = 0; kc < 15; kc++) {
#pragma unroll
        for (int q = 0; q < 4; q++) {
            int idx = tid + q * 256;
            int r = idx >> 3, ju = idx & 7;
            *(uint4*)&As[r][ju * 4] = Ag[(size_t)(m0 + r) * 120 + kc * 8 + ju];
            *(uint4*)&Bs[r][ju * 4] = Bg[(size_t)(n0 + r) * 120 + kc * 8 + ju];
        }
        __syncthreads();
#pragma unroll
        for (int ks = 0; ks < 4; ks++) {
            uint32_t af[4][4], bfr[4][2];
#pragma unroll
            for (int m = 0; m < 4; m++) {
                int r0 = warp_m + m * 16 + g;
                af[m][0] = As[r0][ks * 8 + tg];
                af[m][1] = As[r0 + 8][ks * 8 + tg];
                af[m][2] = As[r0][ks * 8 + tg + 4];
                af[m][3] = As[r0 + 8][ks * 8 + tg + 4];
            }
#pragma unroll
            for (int n = 0; n < 4; n++) {
                int rn = warp_n + n * 8 + g;
                bfr[n][0] = Bs[rn][ks * 8 + tg];
                bfr[n][1] = Bs[rn][ks * 8 + tg + 4];
            }
#pragma unroll
            for (int m = 0; m < 4; m++)
#pragma unroll
                for (int n = 0; n < 4; n++) mma16816(acc[m][n], af[m], bfr[n]);
        }
        __syncthreads();
    }

#pragma unroll
    for (int m = 0; m < 4; m++) {
        int l0 = warp_m + m * 16 + g;
        int l1 = l0 + 8;
        int t0 = d ? (Ldim - 1 - l0) : l0;
        int t1 = d ? (Ldim - 1 - l1) : l1;
        float* base0 = g_PROJ + (((size_t)c * Ldim + t0) * Bdim + b_i) * G4 + g0 + warp_n;
        float* base1 = g_PROJ + (((size_t)c * Ldim + t1) * Bdim + b_i) * G4 + g0 + warp_n;
#pragma unroll
        for (int n = 0; n < 4; n++) {
            int cc = n * 8 + 2 * tg;
            float2 v0 = { acc[m][n][0] + biasS[warp_n + cc],
                          acc[m][n][1] + biasS[warp_n + cc + 1] };
            float2 v1 = { acc[m][n][2] + biasS[warp_n + cc],
                          acc[m][n][3] + biasS[warp_n + cc + 1] };
            *(float2*)(base0 + cc) = v0;
            *(float2*)(base1 + cc) = v1;
        }
    }
}

// ---------------- LSTM recurrence: batch-partitioned, 512 threads, reg-prefetch ----------------
// grid 80 = 10 chains x 8 batch-slices of 16 rows. 16 warps; warp w owns 64 gate
// cols (8 nt-tiles of the old (w>>1) 128-col group, offset (w&1)*8). h stays
// CTA-private in SMEM; W streamed from L2 with 8-wide register prefetch per kt.
__global__ __launch_bounds__(512, 1) void lstm_batch_kernel()
{
    __shared__ uint32_t Hhi[16][132];
    __shared__ uint32_t Hlo[16][132];

    const int bid = blockIdx.x;
    const int c = bid >> 3, s = bid & 7;
    const int b0 = s * 16;
    const int e = c >> 1, d = c & 1;
    const int tid = threadIdx.x;
    const int warp = tid >> 5, lane = tid & 31;      // warp 0..15
    const int wOld = warp >> 1;
    const int ntB = (warp & 1) * 8;                  // nt offset within old group
    const int g = lane >> 2, tg = lane & 3;
    const bool evenp = (tg & 1) == 0;

    const uint4* Wbase = g_wT + ((size_t)c * 8 + wOld) * 256 * 32;

    float cst[8];
#pragma unroll
    for (int i = 0; i < 8; i++) cst[i] = 0.0f;

    for (int t = 0; t < Ldim; t++) {
        float acc[8][4];
#pragma unroll
        for (int nt = 0; nt < 8; nt++)
#pragma unroll
            for (int q = 0; q < 4; q++) acc[nt][q] = 0.0f;

        if (t > 0) {
#pragma unroll 2
            for (int kt = 0; kt < 16; kt++) {
                // prefetch all 8 W fragments for this kt (MLP = 8)
                const uint4* wrow = Wbase + kt * 16 * 32 + (ntB * 32 + lane);
                uint4 wv[8];
#pragma unroll
                for (int nt = 0; nt < 8; nt++) wv[nt] = __ldcg(wrow + nt * 32);

                uint32_t ah[4], al[4];
                ah[0] = Hhi[g][kt * 8 + tg];
                ah[1] = Hhi[g + 8][kt * 8 + tg];
                ah[2] = Hhi[g][kt * 8 + tg + 4];
                ah[3] = Hhi[g + 8][kt * 8 + tg + 4];
                al[0] = Hlo[g][kt * 8 + tg];
                al[1] = Hlo[g + 8][kt * 8 + tg];
                al[2] = Hlo[g][kt * 8 + tg + 4];
                al[3] = Hlo[g + 8][kt * 8 + tg + 4];
#pragma unroll
                for (int nt = 0; nt < 8; nt++) {
                    uint32_t bh[2] = { wv[nt].x, wv[nt].y };
                    uint32_t bl[2] = { wv[nt].z, wv[nt].w };
                    mma16816(acc[nt], ah, bh);
                    mma16816(acc[nt], ah, bl);
                    mma16816(acc[nt], al, bh);
                }
            }
        }
        __syncthreads();   // all A-frag reads of step t done before h overwrite

        // ---- pointwise: gate exchange (xor 1), LSTM cell, h -> SMEM + g_HS ----
        const int lo_t = d ? (Ldim - 1 - t) : t;
        const float* projb = g_PROJ + (((size_t)c * Ldim + t) * Bdim + b0) * G4;
        const int row = g + (evenp ? 0 : 8);
#pragma unroll
        for (int nt = 0; nt < 8; nt++) {
            int ntg = ntB + nt;
            float a0 = acc[nt][0], a1 = acc[nt][1];
            float a2 = acc[nt][2], a3 = acc[nt][3];
            float t0 = __shfl_xor_sync(0xFFFFFFFFu, a0, 1);
            float t1 = __shfl_xor_sync(0xFFFFFFFFu, a1, 1);
            float t2 = __shfl_xor_sync(0xFFFFFFFFu, a2, 1);
            float t3 = __shfl_xor_sync(0xFFFFFFFFu, a3, 1);
            int hd = wOld * 32 + ntg * 2 + (tg >> 1);
            float4 pj = *(const float4*)(projb + (size_t)row * G4 + hd * 4);
            float gi = (evenp ? a0 : t2) + pj.x;
            float gf = (evenp ? a1 : t3) + pj.y;
            float gg = (evenp ? t0 : a2) + pj.z;
            float go = (evenp ? t1 : a3) + pj.w;
            float cn = sigf(gf) * cst[nt] + sigf(gi) * tanh_fast(gg);
            cst[nt] = cn;
            float h = sigf(go) * tanh_fast(cn);
            g_HS[(((size_t)e * Bdim + (b0 + row)) * Ldim + lo_t) * H2 + d * Hdim + hd] = h;
            // pack (even hd, odd hd) pair: partner = lane xor 2 (same row)
            float hB = __shfl_xor_sync(0xFFFFFFFFu, h, 2);
            if ((tg >> 1) == 0) {
                __nv_bfloat16 hhA = __float2bfloat16(h);
                __nv_bfloat16 hhB = __float2bfloat16(hB);
                Hhi[row][wOld * 16 + ntg] = pack_bf2(hhA, hhB);
                Hlo[row][wOld * 16 + ntg] = pack_bf2(
                    __float2bfloat16(h - __bfloat162float(hhA)),
                    __float2bfloat16(hB - __bfloat162float(hhB)));
            }
        }
        __syncthreads();   // h writes visible before next step's A-frag reads
    }
}

// ---------------- attention logits GEMM (mma.sync bf16) ----------------
__global__ __launch_bounds__(256) void attn_mma_kernel(
    const float* __restrict__ attb, const float* __restrict__ attv)
{
    __shared__ __align__(16) uint32_t As[128][36];
    __shared__ __align__(16) uint32_t Bs[128][36];
    __shared__ float red[128][17];

    const int tid = threadIdx.x;
    const int warp = tid >> 5, lane = tid & 31;
    const int g = lane >> 2, tg = lane & 3;
    const int warp_m = (warp >> 2) * 64;
    const int warp_n = (warp & 3) * 32;

    const int m0 = blockIdx.x * 128;
    const int e = blockIdx.y;

    const uint4* Ag = (const uint4*)g_aA;
    const uint4* Bg = (const uint4*)g_aB;
    const float* abp = attb + (size_t)e * H2;
    const float* avp = attv + (size_t)e * H2;

    float part[4][2];
#pragma unroll
    for (int m = 0; m < 4; m++) { part[m][0] = 0.0f; part[m][1] = 0.0f; }

    for (int nc = 0; nc < 4; nc++) {
        const int n0 = nc * 128;
        float acc[4][4][4];
#pragma unroll
        for (int m = 0; m < 4; m++)
#pragma unroll
            for (int n = 0; n < 4; n++)
#pragma unroll
                for (int q = 0; q < 4; q++) acc[m][n][q] = 0.0f;

        for (int kc = 0; kc < 24; kc++) {
            const int pp = kc >> 3, within = kc & 7;
            const int au4 = (pp == 2 ? 64 : 0) + within * 8;
            const int bu4 = kc * 8;
#pragma unroll
            for (int q = 0; q < 4; q++) {
                int idx = tid + q * 256;
                int r = idx >> 3, ju = idx & 7;
                *(uint4*)&As[r][ju * 4] =
                    Ag[((size_t)e * 16384 + m0 + r) * 128 + au4 + ju];
                *(uint4*)&Bs[r][ju * 4] =
                    Bg[((size_t)e * H2 + n0 + r) * 192 + bu4 + ju];
            }
            __syncthreads();
#pragma unroll
            for (int ks = 0; ks < 4; ks++) {
                uint32_t af[4][4], bfr[4][2];
#pragma unroll
                for (int m = 0; m < 4; m++) {
                    int r0 = warp_m + m * 16 + g;
                    af[m][0] = As[r0][ks * 8 + tg];
                    af[m][1] = As[r0 + 8][ks * 8 + tg];
                    af[m][2] = As[r0][ks * 8 + tg + 4];
                    af[m][3] = As[r0 + 8][ks * 8 + tg + 4];
                }
#pragma unroll
                for (int n = 0; n < 4; n++) {
                    int rn = warp_n + n * 8 + g;
                    bfr[n][0] = Bs[rn][ks * 8 + tg];
                    bfr[n][1] = Bs[rn][ks * 8 + tg + 4];
                }
#pragma unroll
                for (int m = 0; m < 4; m++)
#pragma unroll
                    for (int n = 0; n < 4; n++) mma16816(acc[m][n], af[m], bfr[n]);
            }
            __syncthreads();
        }

#pragma unroll
        for (int n = 0; n < 4; n++) {
            int o = n0 + warp_n + n * 8 + 2 * tg;
            float ab0 = abp[o], ab1 = abp[o + 1];
            float av0 = avp[o], av1 = avp[o + 1];
#pragma unroll
            for (int m = 0; m < 4; m++) {
                part[m][0] += tanh_fast(acc[m][n][0] + ab0) * av0
                            + tanh_fast(acc[m][n][1] + ab1) * av1;
                part[m][1] += tanh_fast(acc[m][n][2] + ab0) * av0
                            + tanh_fast(acc[m][n][3] + ab1) * av1;
            }
        }
    }

#pragma unroll
    for (int m = 0; m < 4; m++) {
        int r0 = warp_m + m * 16 + g;
        red[r0][(warp & 3) * 4 + tg] = part[m][0];
        red[r0 + 8][(warp & 3) * 4 + tg] = part[m][1];
    }
    __syncthreads();
    if (tid < 128) {
        float ss = 0.0f;
#pragma unroll
        for (int q = 0; q < 16; q++) ss += red[tid][q];
        g_s[(size_t)e * Bdim * Ldim + m0 + tid] = ss;
    }
}

// ---------------- softmax over L + weighted pooling ----------------
__global__ __launch_bounds__(128) void softmax_pool_kernel()
{
    const int e = blockIdx.y, b = blockIdx.x;
    __shared__ float wts[Ldim];
    __shared__ float red[128];
    const int tid = threadIdx.x;

    float v = g_s[((size_t)e * Bdim + b) * Ldim + tid];
    red[tid] = v; __syncthreads();
    for (int st = 64; st > 0; st >>= 1) {
        if (tid < st) red[tid] = fmaxf(red[tid], red[tid + st]);
        __syncthreads();
    }
    float mx = red[0]; __syncthreads();
    float ev = expf(v - mx);
    red[tid] = ev; __syncthreads();
    for (int st = 64; st > 0; st >>= 1) {
        if (tid < st) red[tid] += red[tid + st];
        __syncthreads();
    }
    float inv = 1.0f / red[0];
    wts[tid] = ev * inv;
    __syncthreads();

    const float* hrow = g_HS + ((size_t)e * Bdim + b) * Ldim * H2;
    float accv[4] = {0.f, 0.f, 0.f, 0.f};
    for (int l = 0; l < Ldim; l++) {
        float a = wts[l];
        const float* hp = hrow + (size_t)l * H2;
#pragma unroll
        for (int j = 0; j < 4; j++) accv[j] += a * hp[tid + j * 128];
    }
    float* op = g_OUT + ((size_t)e * Bdim + b) * H2;
#pragma unroll
    for (int j = 0; j < 4; j++) op[tid + j * 128] = accv[j];
}

// ---------------- output copy + final FC ----------------
__global__ void copy_out_kernel(float* __restrict__ out)
{
    int i = blockIdx.x * blockDim.x + threadIdx.x;
    if (i < NEx * Bdim * H2) out[256 + i] = g_OUT[i];
}

__global__ __launch_bounds__(128) void final_kernel(
    const int* __restrict__ z, const float* __restrict__ fcW,
    const float* __restrict__ fcb, float* __restrict__ out)
{
    const int b = blockIdx.x;
    const int tid = threadIdx.x;
    const int zi = z[b];
    const float* sel = g_OUT + ((size_t)(1 + zi) * Bdim + b) * H2;
    const float* gen = g_OUT + (size_t)b * H2;
    __shared__ float red0[128], red1[128];
    float a0 = 0.f, a1 = 0.f;
    for (int dd = tid; dd < 1024; dd += 128) {
        float cv = (dd < 512) ? sel[dd] : gen[dd - 512];
        a0 += cv * fcW[dd];
        a1 += cv * fcW[1024 + dd];
    }
    red0[tid] = a0; red1[tid] = a1; __syncthreads();
    for (int st = 64; st > 0; st >>= 1) {
        if (tid < st) { red0[tid] += red0[tid + st]; red1[tid] += red1[tid + st]; }
        __syncthreads();
    }
    if (tid == 0) {
        out[b * 2 + 0] = red0[0] + fcb[0];
        out[b * 2 + 1] = red1[0] + fcb[1];
    }
}

// ---------------- launch ----------------
extern "C" void kernel_launch(void* const* d_in, const int* in_sizes, int n_in,
                              void* d_out, int out_size)
{
    (void)in_sizes; (void)n_in; (void)out_size;
    const float* x     = (const float*)d_in[0];
    const int*   z     = (const int*)  d_in[1];
    const float* wih_f = (const float*)d_in[2];
    const float* whh_f = (const float*)d_in[3];
    const float* b_f   = (const float*)d_in[4];
    const float* wih_b = (const float*)d_in[5];
    const float* whh_b = (const float*)d_in[6];
    const float* b_b   = (const float*)d_in[7];
    const float* attW  = (const float*)d_in[8];
    const float* attb  = (const float*)d_in[9];
    const float* attv  = (const float*)d_in[10];
    const float* fcW   = (const float*)d_in[11];
    const float* fcb   = (const float*)d_in[12];
    float* out = (float*)d_out;

    prep_proj_kernel<<<16384 + 10240, 256>>>(x, wih_f, wih_b);
    prep_wT_kernel<<<2560, 256>>>(whh_f, whh_b);
    prep_attnB_kernel<<<NEx * H2, 256>>>(attW);
    proj_mma_kernel<<<dim3(80, 128), 256>>>(b_f, b_b);
    lstm_batch_kernel<<<80, 512>>>();
    prep_attnA_kernel<<<NEx * 16384, 256>>>();
    attn_mma_kernel<<<dim3(128, 5), 256>>>(attb, attv);
    softmax_pool_kernel<<<dim3(128, 5), 128>>>();
    copy_out_kernel<<<(NEx * Bdim * H2 + 255) / 256, 256>>>(out);
    final_kernel<<<128, 128>>>(z, fcW, fcb, out);
}

// round 13
// speedup vs baseline: 1.3933x; 1.0123x over previous
#include <cuda_runtime.h>
#include <cuda_bf16.h>
#include <cstdint>
#include <stdint.h>
#include <math.h>

#define Ldim 128
#define Bdim 128
#define Vdim 300
#define Hdim 256
#define NEx  5
#define NCh  10      // 5 experts x 2 directions
#define G4   1024    // 4*H
#define H2   512     // 2*H
#define KPP  960     // proj K: 3 x 320 (hi, hi, lo sections)
#define KPA  1536    // attn K: 3 x 512

// ---------------- device scratch (no allocations allowed) ----------------
// g_PROJ gate-interleaved: [c][t][b][cg], cg = hd*4 + gate.
__device__ float g_PROJ[(size_t)NCh * Ldim * Bdim * G4];
__device__ float g_HS[(size_t)NEx * Bdim * Ldim * H2];     // [e][b][l][2H]
__device__ float g_s[(size_t)NEx * Bdim * Ldim];           // attention logits
__device__ float g_OUT[(size_t)NEx * Bdim * H2];           // pooled outputs

// bf16 split GEMM operands
__device__ __nv_bfloat16 g_pA[(size_t)16384 * KPP];        // proj A' [m][960]
__device__ __nv_bfloat16 g_pB[(size_t)10240 * KPP];        // proj B' [cg-ordered][960]
__device__ __nv_bfloat16 g_aA[(size_t)NEx * 16384 * 1024]; // attn A [e][m][hi512|lo512]
__device__ __nv_bfloat16 g_aB[(size_t)NEx * H2 * KPA];     // attn B' [e][o][whi|wlo|whi]

// recurrence W_hh as per-lane MMA fragments:
// g_wT[c][w][kt][nt][lane] = uint4 {bh0, bh1, bl0, bl1}  (10 MB total)
__device__ uint4 g_wT[(size_t)NCh * 8 * 16 * 16 * 32];

// ---------------- helpers ----------------
__device__ __forceinline__ float sigf(float x) { return 1.0f / (1.0f + __expf(-x)); }
__device__ __forceinline__ float tanh_fast(float x) {
    float cx = fminf(fmaxf(x, -15.0f), 15.0f);
    float e = __expf(2.0f * cx);
    return (e - 1.0f) / (e + 1.0f);
}
__device__ __forceinline__ void mma16816(float* c, const uint32_t* a, const uint32_t* b) {
    asm volatile(
        "mma.sync.aligned.m16n8k16.row.col.f32.bf16.bf16.f32 "
        "{%0,%1,%2,%3}, {%4,%5,%6,%7}, {%8,%9}, {%0,%1,%2,%3};"
        : "+f"(c[0]), "+f"(c[1]), "+f"(c[2]), "+f"(c[3])
        : "r"(a[0]), "r"(a[1]), "r"(a[2]), "r"(a[3]), "r"(b[0]), "r"(b[1]));
}
__device__ __forceinline__ uint32_t pack_bf2(__nv_bfloat16 a, __nv_bfloat16 b) {
    __nv_bfloat162 p; p.x = a; p.y = b;
    return *(uint32_t*)&p;
}

// ---------------- prep: proj operands (3-term split; B gate-interleaved) ----------------
__global__ __launch_bounds__(256) void prep_proj_kernel(
    const float* __restrict__ x,
    const float* __restrict__ wf, const float* __restrict__ wb)
{
    const int row = blockIdx.x;
    const int tid = threadIdx.x;
    if (row < 16384) {
        const float* src = x + (size_t)row * Vdim;
        __nv_bfloat16* dA = g_pA + (size_t)row * KPP;
        for (int col = tid; col < KPP; col += 256) {
            int s = col / 320, kk = col - s * 320;
            float v = (kk < Vdim) ? src[kk] : 0.0f;
            __nv_bfloat16 hi = __float2bfloat16(v);
            dA[col] = (s < 2) ? hi : __float2bfloat16(v - __bfloat162float(hi));
        }
    } else {
        const int n = row - 16384;                // n = c*1024 + cg
        const int c = n >> 10, e = c >> 1, d = c & 1;
        const int cg = n & 1023;
        const int gt = cg & 3, hd = cg >> 2;
        const float* src = (d ? wb : wf) + ((size_t)e * G4 + gt * 256 + hd) * Vdim;
        __nv_bfloat16* dB = g_pB + (size_t)n * KPP;
        for (int col = tid; col < KPP; col += 256) {
            int s = col / 320, kk = col - s * 320;
            float v = (kk < Vdim) ? src[kk] : 0.0f;
            __nv_bfloat16 hi = __float2bfloat16(v);
            dB[col] = (s == 1) ? __float2bfloat16(v - __bfloat162float(hi)) : hi;
        }
    }
}

// ---------------- prep: W_hh fragment layout ----------------
__global__ __launch_bounds__(256) void prep_wT_kernel(
    const float* __restrict__ whf, const float* __restrict__ whb)
{
    const int idx = blockIdx.x * 256 + threadIdx.x;   // 655360 total
    const int lane = idx & 31;
    const int nt = (idx >> 5) & 15;
    const int kt = (idx >> 9) & 15;
    const int w = (idx >> 13) & 7;
    const int c = idx >> 16;
    const int e = c >> 1, d = c & 1;
    const int cg = w * 128 + nt * 8 + (lane >> 2);
    const int gate = cg & 3, hd = cg >> 2;
    const float* src = (d ? whb : whf) + ((size_t)e * G4 + gate * 256 + hd) * Hdim;
    const int k0 = kt * 16 + (lane & 3) * 2;
    float v00 = src[k0],     v01 = src[k0 + 1];
    float v10 = src[k0 + 8], v11 = src[k0 + 9];
    __nv_bfloat16 h00 = __float2bfloat16(v00), h01 = __float2bfloat16(v01);
    __nv_bfloat16 h10 = __float2bfloat16(v10), h11 = __float2bfloat16(v11);
    uint4 o;
    o.x = pack_bf2(h00, h01);
    o.y = pack_bf2(h10, h11);
    o.z = pack_bf2(__float2bfloat16(v00 - __bfloat162float(h00)),
                   __float2bfloat16(v01 - __bfloat162float(h01)));
    o.w = pack_bf2(__float2bfloat16(v10 - __bfloat162float(h10)),
                   __float2bfloat16(v11 - __bfloat162float(h11)));
    g_wT[idx] = o;
}

// ---------------- prep: attn B' (whi | wlo | whi) ----------------
__global__ __launch_bounds__(256) void prep_attnB_kernel(const float* __restrict__ attW)
{
    const int r = blockIdx.x;                 // e*512 + o
    const int tid = threadIdx.x;
    const float* src = attW + (size_t)r * H2;
    __nv_bfloat16* dB = g_aB + (size_t)r * KPA;
    for (int col = tid; col < KPA; col += 256) {
        int s = col >> 9, kk = col & 511;
        float v = src[kk];
        __nv_bfloat16 hi = __float2bfloat16(v);
        dB[col] = (s == 1) ? __float2bfloat16(v - __bfloat162float(hi)) : hi;
    }
}

// ---------------- prep: attn A (hi | lo of g_HS) ----------------
__global__ __launch_bounds__(256) void prep_attnA_kernel()
{
    const int r = blockIdx.x;                 // e*16384 + m
    const int tid = threadIdx.x;
    const float* src = g_HS + (size_t)r * H2;
    __nv_bfloat16* dA = g_aA + (size_t)r * 1024;
    for (int col = tid; col < 1024; col += 256) {
        int kk = col & 511;
        float v = src[kk];
        __nv_bfloat16 hi = __float2bfloat16(v);
        dA[col] = (col < 512) ? hi : __float2bfloat16(v - __bfloat162float(hi));
    }
}

// ---------------- proj GEMM (mma.sync bf16) ----------------
__global__ __launch_bounds__(256) void proj_mma_kernel(
    const float* __restrict__ bf, const float* __restrict__ bb)
{
    __shared__ __align__(16) uint32_t As[128][36];
    __shared__ __align__(16) uint32_t Bs[128][36];
    __shared__ float biasS[128];

    const int tid = threadIdx.x;
    const int warp = tid >> 5, lane = tid & 31;
    const int g = lane >> 2, tg = lane & 3;
    const int warp_m = (warp >> 2) * 64;
    const int warp_n = (warp & 3) * 32;

    const int n0 = blockIdx.x * 128;
    const int m0 = blockIdx.y * 128;
    const int b_i = blockIdx.y;
    const int c = n0 >> 10, e = c >> 1, d = c & 1;
    const int g0 = n0 & 1023;

    {
        const float* bias = (d ? bb : bf) + (size_t)e * G4;
        if (tid < 128) {
            int cg = g0 + tid;
            biasS[tid] = bias[(cg & 3) * 256 + (cg >> 2)];
        }
    }

    float acc[4][4][4];
#pragma unroll
    for (int m = 0; m < 4; m++)
#pragma unroll
        for (int n = 0; n < 4; n++)
#pragma unroll
            for (int q = 0; q < 4; q++) acc[m][n][q] = 0.0f;

    const uint4* Ag = (const uint4*)g_pA;
    const uint4* Bg = (const uint4*)g_pB;

    for (int kc = 0; kc < 15; kc++) {
#pragma unroll
        for (int q = 0; q < 4; q++) {
            int idx = tid + q * 256;
            int r = idx >> 3, ju = idx & 7;
            *(uint4*)&As[r][ju * 4] = Ag[(size_t)(m0 + r) * 120 + kc * 8 + ju];
            *(uint4*)&Bs[r][ju * 4] = Bg[(size_t)(n0 + r) * 120 + kc * 8 + ju];
        }
        __syncthreads();
#pragma unroll
        for (int ks = 0; ks < 4; ks++) {
            uint32_t af[4][4], bfr[4][2];
#pragma unroll
            for (int m = 0; m < 4; m++) {
                int r0 = warp_m + m * 16 + g;
                af[m][0] = As[r0][ks * 8 + tg];
                af[m][1] = As[r0 + 8][ks * 8 + tg];
                af[m][2] = As[r0][ks * 8 + tg + 4];
                af[m][3] = As[r0 + 8][ks * 8 + tg + 4];
            }
#pragma unroll
            for (int n = 0; n < 4; n++) {
                int rn = warp_n + n * 8 + g;
                bfr[n][0] = Bs[rn][ks * 8 + tg];
                bfr[n][1] = Bs[rn][ks * 8 + tg + 4];
            }
#pragma unroll
            for (int m = 0; m < 4; m++)
#pragma unroll
                for (int n = 0; n < 4; n++) mma16816(acc[m][n], af[m], bfr[n]);
        }
        __syncthreads();
    }

#pragma unroll
    for (int m = 0; m < 4; m++) {
        int l0 = warp_m + m * 16 + g;
        int l1 = l0 + 8;
        int t0 = d ? (Ldim - 1 - l0) : l0;
        int t1 = d ? (Ldim - 1 - l1) : l1;
        float* base0 = g_PROJ + (((size_t)c * Ldim + t0) * Bdim + b_i) * G4 + g0 + warp_n;
        float* base1 = g_PROJ + (((size_t)c * Ldim + t1) * Bdim + b_i) * G4 + g0 + warp_n;
#pragma unroll
        for (int n = 0; n < 4; n++) {
            int cc = n * 8 + 2 * tg;
            float2 v0 = { acc[m][n][0] + biasS[warp_n + cc],
                          acc[m][n][1] + biasS[warp_n + cc + 1] };
            float2 v1 = { acc[m][n][2] + biasS[warp_n + cc],
                          acc[m][n][3] + biasS[warp_n + cc + 1] };
            *(float2*)(base0 + cc) = v0;
            *(float2*)(base1 + cc) = v1;
        }
    }
}

// ---------------- LSTM recurrence: batch-partitioned, 512 threads, kt-pipelined ----------------
// grid 80 = 10 chains x 8 batch-slices of 16 rows. 16 warps; warp w owns 64 gate
// cols. W streamed from L2 with a cross-kt ping-pong register pipeline: MMAs on
// buffer A(kt) overlap the in-flight loads of buffer B(kt+1).
__global__ __launch_bounds__(512, 1) void lstm_batch_kernel()
{
    __shared__ uint32_t Hhi[16][132];
    __shared__ uint32_t Hlo[16][132];

    const int bid = blockIdx.x;
    const int c = bid >> 3, s = bid & 7;
    const int b0 = s * 16;
    const int e = c >> 1, d = c & 1;
    const int tid = threadIdx.x;
    const int warp = tid >> 5, lane = tid & 31;      // warp 0..15
    const int wOld = warp >> 1;
    const int ntB = (warp & 1) * 8;                  // nt offset within old group
    const int g = lane >> 2, tg = lane & 3;
    const bool evenp = (tg & 1) == 0;

    const uint4* Wlane = g_wT + ((size_t)c * 8 + wOld) * 256 * 32 + (ntB * 32 + lane);

    float cst[8];
#pragma unroll
    for (int i = 0; i < 8; i++) cst[i] = 0.0f;

    for (int t = 0; t < Ldim; t++) {
        float acc[8][4];
#pragma unroll
        for (int nt = 0; nt < 8; nt++)
#pragma unroll
            for (int q = 0; q < 4; q++) acc[nt][q] = 0.0f;

        if (t > 0) {
            uint4 bufA[8], bufB[8];
            // prologue: load kt=0 into bufA
#pragma unroll
            for (int nt = 0; nt < 8; nt++) bufA[nt] = __ldcg(Wlane + nt * 32);

            for (int ktp = 0; ktp < 8; ktp++) {
                const int kt0 = 2 * ktp, kt1 = 2 * ktp + 1;
                // prefetch kt1 into bufB (in flight during kt0 MMAs)
                {
                    const uint4* wr = Wlane + kt1 * 512;
#pragma unroll
                    for (int nt = 0; nt < 8; nt++) bufB[nt] = __ldcg(wr + nt * 32);
                }
                // MMA kt0 from bufA
                {
                    uint32_t ah[4], al[4];
                    ah[0] = Hhi[g][kt0 * 8 + tg];
                    ah[1] = Hhi[g + 8][kt0 * 8 + tg];
                    ah[2] = Hhi[g][kt0 * 8 + tg + 4];
                    ah[3] = Hhi[g + 8][kt0 * 8 + tg + 4];
                    al[0] = Hlo[g][kt0 * 8 + tg];
                    al[1] = Hlo[g + 8][kt0 * 8 + tg];
                    al[2] = Hlo[g][kt0 * 8 + tg + 4];
                    al[3] = Hlo[g + 8][kt0 * 8 + tg + 4];
#pragma unroll
                    for (int nt = 0; nt < 8; nt++) {
                        uint32_t bh[2] = { bufA[nt].x, bufA[nt].y };
                        uint32_t bl[2] = { bufA[nt].z, bufA[nt].w };
                        mma16816(acc[nt], ah, bh);
                        mma16816(acc[nt], ah, bl);
                        mma16816(acc[nt], al, bh);
                    }
                }
                // prefetch kt0+2 into bufA (in flight during kt1 MMAs)
                if (ktp < 7) {
                    const uint4* wr = Wlane + (kt0 + 2) * 512;
#pragma unroll
                    for (int nt = 0; nt < 8; nt++) bufA[nt] = __ldcg(wr + nt * 32);
                }
                // MMA kt1 from bufB
                {
                    uint32_t ah[4], al[4];
                    ah[0] = Hhi[g][kt1 * 8 + tg];
                    ah[1] = Hhi[g + 8][kt1 * 8 + tg];
                    ah[2] = Hhi[g][kt1 * 8 + tg + 4];
                    ah[3] = Hhi[g + 8][kt1 * 8 + tg + 4];
                    al[0] = Hlo[g][kt1 * 8 + tg];
                    al[1] = Hlo[g + 8][kt1 * 8 + tg];
                    al[2] = Hlo[g][kt1 * 8 + tg + 4];
                    al[3] = Hlo[g + 8][kt1 * 8 + tg + 4];
#pragma unroll
                    for (int nt = 0; nt < 8; nt++) {
                        uint32_t bh[2] = { bufB[nt].x, bufB[nt].y };
                        uint32_t bl[2] = { bufB[nt].z, bufB[nt].w };
                        mma16816(acc[nt], ah, bh);
                        mma16816(acc[nt], ah, bl);
                        mma16816(acc[nt], al, bh);
                    }
                }
            }
        }
        __syncthreads();   // all A-frag reads of step t done before h overwrite

        // ---- pointwise: gate exchange (xor 1), LSTM cell, h -> SMEM + g_HS ----
        const int lo_t = d ? (Ldim - 1 - t) : t;
        const float* projb = g_PROJ + (((size_t)c * Ldim + t) * Bdim + b0) * G4;
        const int row = g + (evenp ? 0 : 8);
#pragma unroll
        for (int nt = 0; nt < 8; nt++) {
            int ntg = ntB + nt;
            float a0 = acc[nt][0], a1 = acc[nt][1];
            float a2 = acc[nt][2], a3 = acc[nt][3];
            float t0 = __shfl_xor_sync(0xFFFFFFFFu, a0, 1);
            float t1 = __shfl_xor_sync(0xFFFFFFFFu, a1, 1);
            float t2 = __shfl_xor_sync(0xFFFFFFFFu, a2, 1);
            float t3 = __shfl_xor_sync(0xFFFFFFFFu, a3, 1);
            int hd = wOld * 32 + ntg * 2 + (tg >> 1);
            float4 pj = *(const float4*)(projb + (size_t)row * G4 + hd * 4);
            float gi = (evenp ? a0 : t2) + pj.x;
            float gf = (evenp ? a1 : t3) + pj.y;
            float gg = (evenp ? t0 : a2) + pj.z;
            float go = (evenp ? t1 : a3) + pj.w;
            float cn = sigf(gf) * cst[nt] + sigf(gi) * tanh_fast(gg);
            cst[nt] = cn;
            float h = sigf(go) * tanh_fast(cn);
            g_HS[(((size_t)e * Bdim + (b0 + row)) * Ldim + lo_t) * H2 + d * Hdim + hd] = h;
            // pack (even hd, odd hd) pair: partner = lane xor 2 (same row)
            float hB = __shfl_xor_sync(0xFFFFFFFFu, h, 2);
            if ((tg >> 1) == 0) {
                __nv_bfloat16 hhA = __float2bfloat16(h);
                __nv_bfloat16 hhB = __float2bfloat16(hB);
                Hhi[row][wOld * 16 + ntg] = pack_bf2(hhA, hhB);
                Hlo[row][wOld * 16 + ntg] = pack_bf2(
                    __float2bfloat16(h - __bfloat162float(hhA)),
                    __float2bfloat16(hB - __bfloat162float(hhB)));
            }
        }
        __syncthreads();   // h writes visible before next step's A-frag reads
    }
}

// ---------------- attention logits GEMM (mma.sync bf16) ----------------
__global__ __launch_bounds__(256) void attn_mma_kernel(
    const float* __restrict__ attb, const float* __restrict__ attv)
{
    __shared__ __align__(16) uint32_t As[128][36];
    __shared__ __align__(16) uint32_t Bs[128][36];
    __shared__ float red[128][17];

    const int tid = threadIdx.x;
    const int warp = tid >> 5, lane = tid & 31;
    const int g = lane >> 2, tg = lane & 3;
    const int warp_m = (warp >> 2) * 64;
    const int warp_n = (warp & 3) * 32;

    const int m0 = blockIdx.x * 128;
    const int e = blockIdx.y;

    const uint4* Ag = (const uint4*)g_aA;
    const uint4* Bg = (const uint4*)g_aB;
    const float* abp = attb + (size_t)e * H2;
    const float* avp = attv + (size_t)e * H2;

    float part[4][2];
#pragma unroll
    for (int m = 0; m < 4; m++) { part[m][0] = 0.0f; part[m][1] = 0.0f; }

    for (int nc = 0; nc < 4; nc++) {
        const int n0 = nc * 128;
        float acc[4][4][4];
#pragma unroll
        for (int m = 0; m < 4; m++)
#pragma unroll
            for (int n = 0; n < 4; n++)
#pragma unroll
                for (int q = 0; q < 4; q++) acc[m][n][q] = 0.0f;

        for (int kc = 0; kc < 24; kc++) {
            const int pp = kc >> 3, within = kc & 7;
            const int au4 = (pp == 2 ? 64 : 0) + within * 8;
            const int bu4 = kc * 8;
#pragma unroll
            for (int q = 0; q < 4; q++) {
                int idx = tid + q * 256;
                int r = idx >> 3, ju = idx & 7;
                *(uint4*)&As[r][ju * 4] =
                    Ag[((size_t)e * 16384 + m0 + r) * 128 + au4 + ju];
                *(uint4*)&Bs[r][ju * 4] =
                    Bg[((size_t)e * H2 + n0 + r) * 192 + bu4 + ju];
            }
            __syncthreads();
#pragma unroll
            for (int ks = 0; ks < 4; ks++) {
                uint32_t af[4][4], bfr[4][2];
#pragma unroll
                for (int m = 0; m < 4; m++) {
                    int r0 = warp_m + m * 16 + g;
                    af[m][0] = As[r0][ks * 8 + tg];
                    af[m][1] = As[r0 + 8][ks * 8 + tg];
                    af[m][2] = As[r0][ks * 8 + tg + 4];
                    af[m][3] = As[r0 + 8][ks * 8 + tg + 4];
                }
#pragma unroll
                for (int n = 0; n < 4; n++) {
                    int rn = warp_n + n * 8 + g;
                    bfr[n][0] = Bs[rn][ks * 8 + tg];
                    bfr[n][1] = Bs[rn][ks * 8 + tg + 4];
                }
#pragma unroll
                for (int m = 0; m < 4; m++)
#pragma unroll
                    for (int n = 0; n < 4; n++) mma16816(acc[m][n], af[m], bfr[n]);
            }
            __syncthreads();
        }

#pragma unroll
        for (int n = 0; n < 4; n++) {
            int o = n0 + warp_n + n * 8 + 2 * tg;
            float ab0 = abp[o], ab1 = abp[o + 1];
            float av0 = avp[o], av1 = avp[o + 1];
#pragma unroll
            for (int m = 0; m < 4; m++) {
                part[m][0] += tanh_fast(acc[m][n][0] + ab0) * av0
                            + tanh_fast(acc[m][n][1] + ab1) * av1;
                part[m][1] += tanh_fast(acc[m][n][2] + ab0) * av0
                            + tanh_fast(acc[m][n][3] + ab1) * av1;
            }
        }
    }

#pragma unroll
    for (int m = 0; m < 4; m++) {
        int r0 = warp_m + m * 16 + g;
        red[r0][(warp & 3) * 4 + tg] = part[m][0];
        red[r0 + 8][(warp & 3) * 4 + tg] = part[m][1];
    }
    __syncthreads();
    if (tid < 128) {
        float ss = 0.0f;
#pragma unroll
        for (int q = 0; q < 16; q++) ss += red[tid][q];
        g_s[(size_t)e * Bdim * Ldim + m0 + tid] = ss;
    }
}

// ---------------- softmax over L + weighted pooling ----------------
__global__ __launch_bounds__(128) void softmax_pool_kernel()
{
    const int e = blockIdx.y, b = blockIdx.x;
    __shared__ float wts[Ldim];
    __shared__ float red[128];
    const int tid = threadIdx.x;

    float v = g_s[((size_t)e * Bdim + b) * Ldim + tid];
    red[tid] = v; __syncthreads();
    for (int st = 64; st > 0; st >>= 1) {
        if (tid < st) red[tid] = fmaxf(red[tid], red[tid + st]);
        __syncthreads();
    }
    float mx = red[0]; __syncthreads();
    float ev = expf(v - mx);
    red[tid] = ev; __syncthreads();
    for (int st = 64; st > 0; st >>= 1) {
        if (tid < st) red[tid] += red[tid + st];
        __syncthreads();
    }
    float inv = 1.0f / red[0];
    wts[tid] = ev * inv;
    __syncthreads();

    const float* hrow = g_HS + ((size_t)e * Bdim + b) * Ldim * H2;
    float accv[4] = {0.f, 0.f, 0.f, 0.f};
    for (int l = 0; l < Ldim; l++) {
        float a = wts[l];
        const float* hp = hrow + (size_t)l * H2;
#pragma unroll
        for (int j = 0; j < 4; j++) accv[j] += a * hp[tid + j * 128];
    }
    float* op = g_OUT + ((size_t)e * Bdim + b) * H2;
#pragma unroll
    for (int j = 0; j < 4; j++) op[tid + j * 128] = accv[j];
}

// ---------------- output copy + final FC ----------------
__global__ void copy_out_kernel(float* __restrict__ out)
{
    int i = blockIdx.x * blockDim.x + threadIdx.x;
    if (i < NEx * Bdim * H2) out[256 + i] = g_OUT[i];
}

__global__ __launch_bounds__(128) void final_kernel(
    const int* __restrict__ z, const float* __restrict__ fcW,
    const float* __restrict__ fcb, float* __restrict__ out)
{
    const int b = blockIdx.x;
    const int tid = threadIdx.x;
    const int zi = z[b];
    const float* sel = g_OUT + ((size_t)(1 + zi) * Bdim + b) * H2;
    const float* gen = g_OUT + (size_t)b * H2;
    __shared__ float red0[128], red1[128];
    float a0 = 0.f, a1 = 0.f;
    for (int dd = tid; dd < 1024; dd += 128) {
        float cv = (dd < 512) ? sel[dd] : gen[dd - 512];
        a0 += cv * fcW[dd];
        a1 += cv * fcW[1024 + dd];
    }
    red0[tid] = a0; red1[tid] = a1; __syncthreads();
    for (int st = 64; st > 0; st >>= 1) {
        if (tid < st) { red0[tid] += red0[tid + st]; red1[tid] += red1[tid + st]; }
        __syncthreads();
    }
    if (tid == 0) {
        out[b * 2 + 0] = red0[0] + fcb[0];
        out[b * 2 + 1] = red1[0] + fcb[1];
    }
}

// ---------------- launch ----------------
extern "C" void kernel_launch(void* const* d_in, const int* in_sizes, int n_in,
                              void* d_out, int out_size)
{
    (void)in_sizes; (void)n_in; (void)out_size;
    const float* x     = (const float*)d_in[0];
    const int*   z     = (const int*)  d_in[1];
    const float* wih_f = (const float*)d_in[2];
    const float* whh_f = (const float*)d_in[3];
    const float* b_f   = (const float*)d_in[4];
    const float* wih_b = (const float*)d_in[5];
    const float* whh_b = (const float*)d_in[6];
    const float* b_b   = (const float*)d_in[7];
    const float* attW  = (const float*)d_in[8];
    const float* attb  = (const float*)d_in[9];
    const float* attv  = (const float*)d_in[10];
    const float* fcW   = (const float*)d_in[11];
    const float* fcb   = (const float*)d_in[12];
    float* out = (float*)d_out;

    prep_proj_kernel<<<16384 + 10240, 256>>>(x, wih_f, wih_b);
    prep_wT_kernel<<<2560, 256>>>(whh_f, whh_b);
    prep_attnB_kernel<<<NEx * H2, 256>>>(attW);
    proj_mma_kernel<<<dim3(80, 128), 256>>>(b_f, b_b);
    lstm_batch_kernel<<<80, 512>>>();
    prep_attnA_kernel<<<NEx * 16384, 256>>>();
    attn_mma_kernel<<<dim3(128, 5), 256>>>(attb, attv);
    softmax_pool_kernel<<<dim3(128, 5), 128>>>();
    copy_out_kernel<<<(NEx * Bdim * H2 + 255) / 256, 256>>>(out);
    final_kernel<<<128, 128>>>(z, fcW, fcb, out);
}

// round 14
// speedup vs baseline: 1.5461x; 1.1097x over previous
#include <cuda_runtime.h>
#include <cuda_bf16.h>
#include <cuda_fp16.h>
#include <cstdint>
#include <stdint.h>
#include <math.h>

#define Ldim 128
#define Bdim 128
#define Vdim 300
#define Hdim 256
#define NEx  5
#define NCh  10      // 5 experts x 2 directions
#define G4   1024    // 4*H
#define H2   512     // 2*H
#define KPP  960     // proj K: 3 x 320 (hi, hi, lo sections)
#define KPA  1536    // attn K: 3 x 512

// ---------------- device scratch (no allocations allowed) ----------------
// g_PROJ gate-interleaved: [c][t][b][cg], cg = hd*4 + gate.
__device__ float g_PROJ[(size_t)NCh * Ldim * Bdim * G4];
__device__ float g_HS[(size_t)NEx * Bdim * Ldim * H2];     // [e][b][l][2H]
__device__ float g_s[(size_t)NEx * Bdim * Ldim];           // attention logits
__device__ float g_OUT[(size_t)NEx * Bdim * H2];           // pooled outputs

// bf16 split GEMM operands (proj / attn, unchanged)
__device__ __nv_bfloat16 g_pA[(size_t)16384 * KPP];
__device__ __nv_bfloat16 g_pB[(size_t)10240 * KPP];
__device__ __nv_bfloat16 g_aA[(size_t)NEx * 16384 * 1024];
__device__ __nv_bfloat16 g_aB[(size_t)NEx * H2 * KPA];

// recurrence W_hh as per-lane fp16 MMA fragments (single precision term):
// g_wT[c][w][kt][nt][lane] = uint2 {h2(v00,v01), h2(v10,v11)}  (5 MB)
__device__ uint2 g_wT[(size_t)NCh * 8 * 16 * 16 * 32];

// ---------------- helpers ----------------
__device__ __forceinline__ float sigf(float x) { return 1.0f / (1.0f + __expf(-x)); }
__device__ __forceinline__ float tanh_fast(float x) {
    float cx = fminf(fmaxf(x, -15.0f), 15.0f);
    float e = __expf(2.0f * cx);
    return (e - 1.0f) / (e + 1.0f);
}
__device__ __forceinline__ void mma16816(float* c, const uint32_t* a, const uint32_t* b) {
    asm volatile(
        "mma.sync.aligned.m16n8k16.row.col.f32.bf16.bf16.f32 "
        "{%0,%1,%2,%3}, {%4,%5,%6,%7}, {%8,%9}, {%0,%1,%2,%3};"
        : "+f"(c[0]), "+f"(c[1]), "+f"(c[2]), "+f"(c[3])
        : "r"(a[0]), "r"(a[1]), "r"(a[2]), "r"(a[3]), "r"(b[0]), "r"(b[1]));
}
__device__ __forceinline__ void mma16816h(float* c, const uint32_t* a, const uint32_t* b) {
    asm volatile(
        "mma.sync.aligned.m16n8k16.row.col.f32.f16.f16.f32 "
        "{%0,%1,%2,%3}, {%4,%5,%6,%7}, {%8,%9}, {%0,%1,%2,%3};"
        : "+f"(c[0]), "+f"(c[1]), "+f"(c[2]), "+f"(c[3])
        : "r"(a[0]), "r"(a[1]), "r"(a[2]), "r"(a[3]), "r"(b[0]), "r"(b[1]));
}
__device__ __forceinline__ uint32_t pack_bf2(__nv_bfloat16 a, __nv_bfloat16 b) {
    __nv_bfloat162 p; p.x = a; p.y = b;
    return *(uint32_t*)&p;
}
__device__ __forceinline__ uint32_t pack_h2(float a, float b) {
    __half2 p = __floats2half2_rn(a, b);
    return *(uint32_t*)&p;
}

// ---------------- prep: proj operands (3-term bf16 split; B gate-interleaved) ----------------
__global__ __launch_bounds__(256) void prep_proj_kernel(
    const float* __restrict__ x,
    const float* __restrict__ wf, const float* __restrict__ wb)
{
    const int row = blockIdx.x;
    const int tid = threadIdx.x;
    if (row < 16384) {
        const float* src = x + (size_t)row * Vdim;
        __nv_bfloat16* dA = g_pA + (size_t)row * KPP;
        for (int col = tid; col < KPP; col += 256) {
            int s = col / 320, kk = col - s * 320;
            float v = (kk < Vdim) ? src[kk] : 0.0f;
            __nv_bfloat16 hi = __float2bfloat16(v);
            dA[col] = (s < 2) ? hi : __float2bfloat16(v - __bfloat162float(hi));
        }
    } else {
        const int n = row - 16384;                // n = c*1024 + cg
        const int c = n >> 10, e = c >> 1, d = c & 1;
        const int cg = n & 1023;
        const int gt = cg & 3, hd = cg >> 2;
        const float* src = (d ? wb : wf) + ((size_t)e * G4 + gt * 256 + hd) * Vdim;
        __nv_bfloat16* dB = g_pB + (size_t)n * KPP;
        for (int col = tid; col < KPP; col += 256) {
            int s = col / 320, kk = col - s * 320;
            float v = (kk < Vdim) ? src[kk] : 0.0f;
            __nv_bfloat16 hi = __float2bfloat16(v);
            dB[col] = (s == 1) ? __float2bfloat16(v - __bfloat162float(hi)) : hi;
        }
    }
}

// ---------------- prep: W_hh fp16 fragment layout ----------------
__global__ __launch_bounds__(256) void prep_wT_kernel(
    const float* __restrict__ whf, const float* __restrict__ whb)
{
    const int idx = blockIdx.x * 256 + threadIdx.x;   // 655360 total
    const int lane = idx & 31;
    const int nt = (idx >> 5) & 15;
    const int kt = (idx >> 9) & 15;
    const int w = (idx >> 13) & 7;
    const int c = idx >> 16;
    const int e = c >> 1, d = c & 1;
    const int cg = w * 128 + nt * 8 + (lane >> 2);
    const int gate = cg & 3, hd = cg >> 2;
    const float* src = (d ? whb : whf) + ((size_t)e * G4 + gate * 256 + hd) * Hdim;
    const int k0 = kt * 16 + (lane & 3) * 2;
    uint2 o;
    o.x = pack_h2(src[k0], src[k0 + 1]);
    o.y = pack_h2(src[k0 + 8], src[k0 + 9]);
    g_wT[idx] = o;
}

// ---------------- prep: attn B' (whi | wlo | whi) ----------------
__global__ __launch_bounds__(256) void prep_attnB_kernel(const float* __restrict__ attW)
{
    const int r = blockIdx.x;                 // e*512 + o
    const int tid = threadIdx.x;
    const float* src = attW + (size_t)r * H2;
    __nv_bfloat16* dB = g_aB + (size_t)r * KPA;
    for (int col = tid; col < KPA; col += 256) {
        int s = col >> 9, kk = col & 511;
        float v = src[kk];
        __nv_bfloat16 hi = __float2bfloat16(v);
        dB[col] = (s == 1) ? __float2bfloat16(v - __bfloat162float(hi)) : hi;
    }
}

// ---------------- prep: attn A (hi | lo of g_HS) ----------------
__global__ __launch_bounds__(256) void prep_attnA_kernel()
{
    const int r = blockIdx.x;                 // e*16384 + m
    const int tid = threadIdx.x;
    const float* src = g_HS + (size_t)r * H2;
    __nv_bfloat16* dA = g_aA + (size_t)r * 1024;
    for (int col = tid; col < 1024; col += 256) {
        int kk = col & 511;
        float v = src[kk];
        __nv_bfloat16 hi = __float2bfloat16(v);
        dA[col] = (col < 512) ? hi : __float2bfloat16(v - __bfloat162float(hi));
    }
}

// ---------------- proj GEMM (mma.sync bf16) ----------------
__global__ __launch_bounds__(256) void proj_mma_kernel(
    const float* __restrict__ bf, const float* __restrict__ bb)
{
    __shared__ __align__(16) uint32_t As[128][36];
    __shared__ __align__(16) uint32_t Bs[128][36];
    __shared__ float biasS[128];

    const int tid = threadIdx.x;
    const int warp = tid >> 5, lane = tid & 31;
    const int g = lane >> 2, tg = lane & 3;
    const int warp_m = (warp >> 2) * 64;
    const int warp_n = (warp & 3) * 32;

    const int n0 = blockIdx.x * 128;
    const int m0 = blockIdx.y * 128;
    const int b_i = blockIdx.y;
    const int c = n0 >> 10, e = c >> 1, d = c & 1;
    const int g0 = n0 & 1023;

    {
        const float* bias = (d ? bb : bf) + (size_t)e * G4;
        if (tid < 128) {
            int cg = g0 + tid;
            biasS[tid] = bias[(cg & 3) * 256 + (cg >> 2)];
        }
    }

    float acc[4][4][4];
#pragma unroll
    for (int m = 0; m < 4; m++)
#pragma unroll
        for (int n = 0; n < 4; n++)
#pragma unroll
            for (int q = 0; q < 4; q++) acc[m][n][q] = 0.0f;

    const uint4* Ag = (const uint4*)g_pA;
    const uint4* Bg = (const uint4*)g_pB;

    for (int kc = 0; kc < 15; kc++) {
#pragma unroll
        for (int q = 0; q < 4; q++) {
            int idx = tid + q * 256;
            int r = idx >> 3, ju = idx & 7;
            *(uint4*)&As[r][ju * 4] = Ag[(size_t)(m0 + r) * 120 + kc * 8 + ju];
            *(uint4*)&Bs[r][ju * 4] = Bg[(size_t)(n0 + r) * 120 + kc * 8 + ju];
        }
        __syncthreads();
#pragma unroll
        for (int ks = 0; ks < 4; ks++) {
            uint32_t af[4][4], bfr[4][2];
#pragma unroll
            for (int m = 0; m < 4; m++) {
                int r0 = warp_m + m * 16 + g;
                af[m][0] = As[r0][ks * 8 + tg];
                af[m][1] = As[r0 + 8][ks * 8 + tg];
                af[m][2] = As[r0][ks * 8 + tg + 4];
                af[m][3] = As[r0 + 8][ks * 8 + tg + 4];
            }
#pragma unroll
            for (int n = 0; n < 4; n++) {
                int rn = warp_n + n * 8 + g;
                bfr[n][0] = Bs[rn][ks * 8 + tg];
                bfr[n][1] = Bs[rn][ks * 8 + tg + 4];
            }
#pragma unroll
            for (int m = 0; m < 4; m++)
#pragma unroll
                for (int n = 0; n < 4; n++) mma16816(acc[m][n], af[m], bfr[n]);
        }
        __syncthreads();
    }

#pragma unroll
    for (int m = 0; m < 4; m++) {
        int l0 = warp_m + m * 16 + g;
        int l1 = l0 + 8;
        int t0 = d ? (Ldim - 1 - l0) : l0;
        int t1 = d ? (Ldim - 1 - l1) : l1;
        float* base0 = g_PROJ + (((size_t)c * Ldim + t0) * Bdim + b_i) * G4 + g0 + warp_n;
        float* base1 = g_PROJ + (((size_t)c * Ldim + t1) * Bdim + b_i) * G4 + g0 + warp_n;
#pragma unroll
        for (int n = 0; n < 4; n++) {
            int cc = n * 8 + 2 * tg;
            float2 v0 = { acc[m][n][0] + biasS[warp_n + cc],
                          acc[m][n][1] + biasS[warp_n + cc + 1] };
            float2 v1 = { acc[m][n][2] + biasS[warp_n + cc],
                          acc[m][n][3] + biasS[warp_n + cc + 1] };
            *(float2*)(base0 + cc) = v0;
            *(float2*)(base1 + cc) = v1;
        }
    }
}

// ---------------- LSTM recurrence: fp16 2-term, 512 threads, kt-pipelined ----------------
// grid 80 = 10 chains x 8 batch-slices of 16 rows. W single fp16 (uint2/lane),
// h split into fp16 hi+lo in SMEM. 2 MMAs per (kt,nt): ah*bh + al*bh.
__global__ __launch_bounds__(512, 1) void lstm_batch_kernel()
{
    __shared__ uint32_t Hhi[16][132];
    __shared__ uint32_t Hlo[16][132];

    const int bid = blockIdx.x;
    const int c = bid >> 3, s = bid & 7;
    const int b0 = s * 16;
    const int e = c >> 1, d = c & 1;
    const int tid = threadIdx.x;
    const int warp = tid >> 5, lane = tid & 31;      // warp 0..15
    const int wOld = warp >> 1;
    const int ntB = (warp & 1) * 8;
    const int g = lane >> 2, tg = lane & 3;
    const bool evenp = (tg & 1) == 0;

    const uint2* Wlane = g_wT + ((size_t)c * 8 + wOld) * 256 * 32 + (ntB * 32 + lane);

    float cst[8];
#pragma unroll
    for (int i = 0; i < 8; i++) cst[i] = 0.0f;

    for (int t = 0; t < Ldim; t++) {
        float acc[8][4];
#pragma unroll
        for (int nt = 0; nt < 8; nt++)
#pragma unroll
            for (int q = 0; q < 4; q++) acc[nt][q] = 0.0f;

        if (t > 0) {
            uint2 bufA[8], bufB[8];
#pragma unroll
            for (int nt = 0; nt < 8; nt++) bufA[nt] = __ldcg(Wlane + nt * 32);

            for (int ktp = 0; ktp < 8; ktp++) {
                const int kt0 = 2 * ktp, kt1 = 2 * ktp + 1;
                {
                    const uint2* wr = Wlane + kt1 * 512;
#pragma unroll
                    for (int nt = 0; nt < 8; nt++) bufB[nt] = __ldcg(wr + nt * 32);
                }
                {
                    uint32_t ah[4], al[4];
                    ah[0] = Hhi[g][kt0 * 8 + tg];
                    ah[1] = Hhi[g + 8][kt0 * 8 + tg];
                    ah[2] = Hhi[g][kt0 * 8 + tg + 4];
                    ah[3] = Hhi[g + 8][kt0 * 8 + tg + 4];
                    al[0] = Hlo[g][kt0 * 8 + tg];
                    al[1] = Hlo[g + 8][kt0 * 8 + tg];
                    al[2] = Hlo[g][kt0 * 8 + tg + 4];
                    al[3] = Hlo[g + 8][kt0 * 8 + tg + 4];
#pragma unroll
                    for (int nt = 0; nt < 8; nt++) {
                        uint32_t bh[2] = { bufA[nt].x, bufA[nt].y };
                        mma16816h(acc[nt], ah, bh);
                        mma16816h(acc[nt], al, bh);
                    }
                }
                if (ktp < 7) {
                    const uint2* wr = Wlane + (kt0 + 2) * 512;
#pragma unroll
                    for (int nt = 0; nt < 8; nt++) bufA[nt] = __ldcg(wr + nt * 32);
                }
                {
                    uint32_t ah[4], al[4];
                    ah[0] = Hhi[g][kt1 * 8 + tg];
                    ah[1] = Hhi[g + 8][kt1 * 8 + tg];
                    ah[2] = Hhi[g][kt1 * 8 + tg + 4];
                    ah[3] = Hhi[g + 8][kt1 * 8 + tg + 4];
                    al[0] = Hlo[g][kt1 * 8 + tg];
                    al[1] = Hlo[g + 8][kt1 * 8 + tg];
                    al[2] = Hlo[g][kt1 * 8 + tg + 4];
                    al[3] = Hlo[g + 8][kt1 * 8 + tg + 4];
#pragma unroll
                    for (int nt = 0; nt < 8; nt++) {
                        uint32_t bh[2] = { bufB[nt].x, bufB[nt].y };
                        mma16816h(acc[nt], ah, bh);
                        mma16816h(acc[nt], al, bh);
                    }
                }
            }
        }
        __syncthreads();   // all A-frag reads of step t done before h overwrite

        // ---- pointwise: gate exchange (xor 1), LSTM cell, h -> SMEM + g_HS ----
        const int lo_t = d ? (Ldim - 1 - t) : t;
        const float* projb = g_PROJ + (((size_t)c * Ldim + t) * Bdim + b0) * G4;
        const int row = g + (evenp ? 0 : 8);
#pragma unroll
        for (int nt = 0; nt < 8; nt++) {
            int ntg = ntB + nt;
            float a0 = acc[nt][0], a1 = acc[nt][1];
            float a2 = acc[nt][2], a3 = acc[nt][3];
            float t0 = __shfl_xor_sync(0xFFFFFFFFu, a0, 1);
            float t1 = __shfl_xor_sync(0xFFFFFFFFu, a1, 1);
            float t2 = __shfl_xor_sync(0xFFFFFFFFu, a2, 1);
            float t3 = __shfl_xor_sync(0xFFFFFFFFu, a3, 1);
            int hd = wOld * 32 + ntg * 2 + (tg >> 1);
            float4 pj = *(const float4*)(projb + (size_t)row * G4 + hd * 4);
            float gi = (evenp ? a0 : t2) + pj.x;
            float gf = (evenp ? a1 : t3) + pj.y;
            float gg = (evenp ? t0 : a2) + pj.z;
            float go = (evenp ? t1 : a3) + pj.w;
            float cn = sigf(gf) * cst[nt] + sigf(gi) * tanh_fast(gg);
            cst[nt] = cn;
            float h = sigf(go) * tanh_fast(cn);
            g_HS[(((size_t)e * Bdim + (b0 + row)) * Ldim + lo_t) * H2 + d * Hdim + hd] = h;
            // pack (even hd, odd hd) pair: partner = lane xor 2 (same row)
            float hB = __shfl_xor_sync(0xFFFFFFFFu, h, 2);
            if ((tg >> 1) == 0) {
                float hA_hi; // split h into fp16 hi + lo
                {
                    __half ha = __float2half_rn(h);
                    __half hb = __float2half_rn(hB);
                    hA_hi = __half2float(ha);
                    float hB_hi = __half2float(hb);
                    Hhi[row][wOld * 16 + ntg] = pack_h2(h, hB);   // rn-packed hi
                    Hlo[row][wOld * 16 + ntg] = pack_h2(h - hA_hi, hB - hB_hi);
                }
            }
        }
        __syncthreads();   // h writes visible before next step's A-frag reads
    }
}

// ---------------- attention logits GEMM (mma.sync bf16) ----------------
__global__ __launch_bounds__(256) void attn_mma_kernel(
    const float* __restrict__ attb, const float* __restrict__ attv)
{
    __shared__ __align__(16) uint32_t As[128][36];
    __shared__ __align__(16) uint32_t Bs[128][36];
    __shared__ float red[128][17];

    const int tid = threadIdx.x;
    const int warp = tid >> 5, lane = tid & 31;
    const int g = lane >> 2, tg = lane & 3;
    const int warp_m = (warp >> 2) * 64;
    const int warp_n = (warp & 3) * 32;

    const int m0 = blockIdx.x * 128;
    const int e = blockIdx.y;

    const uint4* Ag = (const uint4*)g_aA;
    const uint4* Bg = (const uint4*)g_aB;
    const float* abp = attb + (size_t)e * H2;
    const float* avp = attv + (size_t)e * H2;

    float part[4][2];
#pragma unroll
    for (int m = 0; m < 4; m++) { part[m][0] = 0.0f; part[m][1] = 0.0f; }

    for (int nc = 0; nc < 4; nc++) {
        const int n0 = nc * 128;
        float acc[4][4][4];
#pragma unroll
        for (int m = 0; m < 4; m++)
#pragma unroll
            for (int n = 0; n < 4; n++)
#pragma unroll
                for (int q = 0; q < 4; q++) acc[m][n][q] = 0.0f;

        for (int kc = 0; kc < 24; kc++) {
            const int pp = kc >> 3, within = kc & 7;
            const int au4 = (pp == 2 ? 64 : 0) + within * 8;
            const int bu4 = kc * 8;
#pragma unroll
            for (int q = 0; q < 4; q++) {
                int idx = tid + q * 256;
                int r = idx >> 3, ju = idx & 7;
                *(uint4*)&As[r][ju * 4] =
                    Ag[((size_t)e * 16384 + m0 + r) * 128 + au4 + ju];
                *(uint4*)&Bs[r][ju * 4] =
                    Bg[((size_t)e * H2 + n0 + r) * 192 + bu4 + ju];
            }
            __syncthreads();
#pragma unroll
            for (int ks = 0; ks < 4; ks++) {
                uint32_t af[4][4], bfr[4][2];
#pragma unroll
                for (int m = 0; m < 4; m++) {
                    int r0 = warp_m + m * 16 + g;
                    af[m][0] = As[r0][ks * 8 + tg];
                    af[m][1] = As[r0 + 8][ks * 8 + tg];
                    af[m][2] = As[r0][ks * 8 + tg + 4];
                    af[m][3] = As[r0 + 8][ks * 8 + tg + 4];
                }
#pragma unroll
                for (int n = 0; n < 4; n++) {
                    int rn = warp_n + n * 8 + g;
                    bfr[n][0] = Bs[rn][ks * 8 + tg];
                    bfr[n][1] = Bs[rn][ks * 8 + tg + 4];
                }
#pragma unroll
                for (int m = 0; m < 4; m++)
#pragma unroll
                    for (int n = 0; n < 4; n++) mma16816(acc[m][n], af[m], bfr[n]);
            }
            __syncthreads();
        }

#pragma unroll
        for (int n = 0; n < 4; n++) {
            int o = n0 + warp_n + n * 8 + 2 * tg;
            float ab0 = abp[o], ab1 = abp[o + 1];
            float av0 = avp[o], av1 = avp[o + 1];
#pragma unroll
            for (int m = 0; m < 4; m++) {
                part[m][0] += tanh_fast(acc[m][n][0] + ab0) * av0
                            + tanh_fast(acc[m][n][1] + ab1) * av1;
                part[m][1] += tanh_fast(acc[m][n][2] + ab0) * av0
                            + tanh_fast(acc[m][n][3] + ab1) * av1;
            }
        }
    }

#pragma unroll
    for (int m = 0; m < 4; m++) {
        int r0 = warp_m + m * 16 + g;
        red[r0][(warp & 3) * 4 + tg] = part[m][0];
        red[r0 + 8][(warp & 3) * 4 + tg] = part[m][1];
    }
    __syncthreads();
    if (tid < 128) {
        float ss = 0.0f;
#pragma unroll
        for (int q = 0; q < 16; q++) ss += red[tid][q];
        g_s[(size_t)e * Bdim * Ldim + m0 + tid] = ss;
    }
}

// ---------------- softmax over L + weighted pooling ----------------
__global__ __launch_bounds__(128) void softmax_pool_kernel()
{
    const int e = blockIdx.y, b = blockIdx.x;
    __shared__ float wts[Ldim];
    __shared__ float red[128];
    const int tid = threadIdx.x;

    float v = g_s[((size_t)e * Bdim + b) * Ldim + tid];
    red[tid] = v; __syncthreads();
    for (int st = 64; st > 0; st >>= 1) {
        if (tid < st) red[tid] = fmaxf(red[tid], red[tid + st]);
        __syncthreads();
    }
    float mx = red[0]; __syncthreads();
    float ev = expf(v - mx);
    red[tid] = ev; __syncthreads();
    for (int st = 64; st > 0; st >>= 1) {
        if (tid < st) red[tid] += red[tid + st];
        __syncthreads();
    }
    float inv = 1.0f / red[0];
    wts[tid] = ev * inv;
    __syncthreads();

    const float* hrow = g_HS + ((size_t)e * Bdim + b) * Ldim * H2;
    float accv[4] = {0.f, 0.f, 0.f, 0.f};
    for (int l = 0; l < Ldim; l++) {
        float a = wts[l];
        const float* hp = hrow + (size_t)l * H2;
#pragma unroll
        for (int j = 0; j < 4; j++) accv[j] += a * hp[tid + j * 128];
    }
    float* op = g_OUT + ((size_t)e * Bdim + b) * H2;
#pragma unroll
    for (int j = 0; j < 4; j++) op[tid + j * 128] = accv[j];
}

// ---------------- output copy + final FC ----------------
__global__ void copy_out_kernel(float* __restrict__ out)
{
    int i = blockIdx.x * blockDim.x + threadIdx.x;
    if (i < NEx * Bdim * H2) out[256 + i] = g_OUT[i];
}

__global__ __launch_bounds__(128) void final_kernel(
    const int* __restrict__ z, const float* __restrict__ fcW,
    const float* __restrict__ fcb, float* __restrict__ out)
{
    const int b = blockIdx.x;
    const int tid = threadIdx.x;
    const int zi = z[b];
    const float* sel = g_OUT + ((size_t)(1 + zi) * Bdim + b) * H2;
    const float* gen = g_OUT + (size_t)b * H2;
    __shared__ float red0[128], red1[128];
    float a0 = 0.f, a1 = 0.f;
    for (int dd = tid; dd < 1024; dd += 128) {
        float cv = (dd < 512) ? sel[dd] : gen[dd - 512];
        a0 += cv * fcW[dd];
        a1 += cv * fcW[1024 + dd];
    }
    red0[tid] = a0; red1[tid] = a1; __syncthreads();
    for (int st = 64; st > 0; st >>= 1) {
        if (tid < st) { red0[tid] += red0[tid + st]; red1[tid] += red1[tid + st]; }
        __syncthreads();
    }
    if (tid == 0) {
        out[b * 2 + 0] = red0[0] + fcb[0];
        out[b * 2 + 1] = red1[0] + fcb[1];
    }
}

// ---------------- launch ----------------
extern "C" void kernel_launch(void* const* d_in, const int* in_sizes, int n_in,
                              void* d_out, int out_size)
{
    (void)in_sizes; (void)n_in; (void)out_size;
    const float* x     = (const float*)d_in[0];
    const int*   z     = (const int*)  d_in[1];
    const float* wih_f = (const float*)d_in[2];
    const float* whh_f = (const float*)d_in[3];
    const float* b_f   = (const float*)d_in[4];
    const float* wih_b = (const float*)d_in[5];
    const float* whh_b = (const float*)d_in[6];
    const float* b_b   = (const float*)d_in[7];
    const float* attW  = (const float*)d_in[8];
    const float* attb  = (const float*)d_in[9];
    const float* attv  = (const float*)d_in[10];
    const float* fcW   = (const float*)d_in[11];
    const float* fcb   = (const float*)d_in[12];
    float* out = (float*)d_out;

    prep_proj_kernel<<<16384 + 10240, 256>>>(x, wih_f, wih_b);
    prep_wT_kernel<<<2560, 256>>>(whh_f, whh_b);
    prep_attnB_kernel<<<NEx * H2, 256>>>(attW);
    proj_mma_kernel<<<dim3(80, 128), 256>>>(b_f, b_b);
    lstm_batch_kernel<<<80, 512>>>();
    prep_attnA_kernel<<<NEx * 16384, 256>>>();
    attn_mma_kernel<<<dim3(128, 5), 256>>>(attb, attv);
    softmax_pool_kernel<<<dim3(128, 5), 128>>>();
    copy_out_kernel<<<(NEx * Bdim * H2 + 255) / 256, 256>>>(out);
    final_kernel<<<128, 128>>>(z, fcW, fcb, out);
}

// round 15
// speedup vs baseline: 1.8311x; 1.1843x over previous
#include <cuda_runtime.h>
#include <cuda_bf16.h>
#include <cuda_fp16.h>
#include <cstdint>
#include <stdint.h>
#include <math.h>

#define Ldim 128
#define Bdim 128
#define Vdim 300
#define Hdim 256
#define NEx  5
#define NCh  10      // 5 experts x 2 directions
#define G4   1024    // 4*H
#define H2   512     // 2*H
#define KPP  640     // proj K: 2 x 320 (x hi, x lo) vs single fp16 W
#define KPA  1024    // attn K: 2 x 512 (h hi, h lo) vs single fp16 W

// ---------------- device scratch (no allocations allowed) ----------------
// g_PROJ gate-interleaved: [c][t][b][cg], cg = hd*4 + gate.
__device__ float g_PROJ[(size_t)NCh * Ldim * Bdim * G4];
__device__ float g_HS[(size_t)NEx * Bdim * Ldim * H2];     // [e][b][l][2H]
__device__ float g_s[(size_t)NEx * Bdim * Ldim];           // attention logits
__device__ float g_OUT[(size_t)NEx * Bdim * H2];           // pooled outputs

// fp16 GEMM operands
__device__ __half g_pA[(size_t)16384 * KPP];               // proj A [m][xhi320|xlo320]
__device__ __half g_pB[(size_t)10240 * KPP];               // proj B [cg][W320|W320]
__device__ __half g_aA[(size_t)NEx * 16384 * KPA];         // attn A [e][m][hi512|lo512]
__device__ __half g_aB[(size_t)NEx * H2 * KPA];            // attn B [e][o][W512|W512]

// recurrence W_hh as per-lane fp16 MMA fragments:
// g_wT[c][w][kt][nt][lane] = uint2 {h2(v00,v01), h2(v10,v11)}  (5 MB)
__device__ uint2 g_wT[(size_t)NCh * 8 * 16 * 16 * 32];

// ---------------- helpers ----------------
__device__ __forceinline__ float sigf(float x) { return 1.0f / (1.0f + __expf(-x)); }
__device__ __forceinline__ float tanh_fast(float x) {
    float cx = fminf(fmaxf(x, -15.0f), 15.0f);
    float e = __expf(2.0f * cx);
    return (e - 1.0f) / (e + 1.0f);
}
__device__ __forceinline__ void mma16816h(float* c, const uint32_t* a, const uint32_t* b) {
    asm volatile(
        "mma.sync.aligned.m16n8k16.row.col.f32.f16.f16.f32 "
        "{%0,%1,%2,%3}, {%4,%5,%6,%7}, {%8,%9}, {%0,%1,%2,%3};"
        : "+f"(c[0]), "+f"(c[1]), "+f"(c[2]), "+f"(c[3])
        : "r"(a[0]), "r"(a[1]), "r"(a[2]), "r"(a[3]), "r"(b[0]), "r"(b[1]));
}
__device__ __forceinline__ uint32_t pack_h2(float a, float b) {
    __half2 p = __floats2half2_rn(a, b);
    return *(uint32_t*)&p;
}

// ---------------- prep: proj operands (x hi/lo fp16; W single fp16 duplicated) ----------------
__global__ __launch_bounds__(256) void prep_proj_kernel(
    const float* __restrict__ x,
    const float* __restrict__ wf, const float* __restrict__ wb)
{
    const int row = blockIdx.x;
    const int tid = threadIdx.x;
    if (row < 16384) {
        const float* src = x + (size_t)row * Vdim;
        __half* dA = g_pA + (size_t)row * KPP;
        for (int col = tid; col < KPP; col += 256) {
            int s = col / 320, kk = col - s * 320;
            float v = (kk < Vdim) ? src[kk] : 0.0f;
            __half hi = __float2half_rn(v);
            dA[col] = (s == 0) ? hi : __float2half_rn(v - __half2float(hi));
        }
    } else {
        const int n = row - 16384;                // n = c*1024 + cg
        const int c = n >> 10, e = c >> 1, d = c & 1;
        const int cg = n & 1023;
        const int gt = cg & 3, hd = cg >> 2;
        const float* src = (d ? wb : wf) + ((size_t)e * G4 + gt * 256 + hd) * Vdim;
        __half* dB = g_pB + (size_t)n * KPP;
        for (int col = tid; col < KPP; col += 256) {
            int s = col / 320, kk = col - s * 320;
            (void)s;
            float v = (kk < Vdim) ? src[kk] : 0.0f;
            dB[col] = __float2half_rn(v);          // same W in both sections
        }
    }
}

// ---------------- prep: W_hh fp16 fragment layout ----------------
__global__ __launch_bounds__(256) void prep_wT_kernel(
    const float* __restrict__ whf, const float* __restrict__ whb)
{
    const int idx = blockIdx.x * 256 + threadIdx.x;   // 655360 total
    const int lane = idx & 31;
    const int nt = (idx >> 5) & 15;
    const int kt = (idx >> 9) & 15;
    const int w = (idx >> 13) & 7;
    const int c = idx >> 16;
    const int e = c >> 1, d = c & 1;
    const int cg = w * 128 + nt * 8 + (lane >> 2);
    const int gate = cg & 3, hd = cg >> 2;
    const float* src = (d ? whb : whf) + ((size_t)e * G4 + gate * 256 + hd) * Hdim;
    const int k0 = kt * 16 + (lane & 3) * 2;
    uint2 o;
    o.x = pack_h2(src[k0], src[k0 + 1]);
    o.y = pack_h2(src[k0 + 8], src[k0 + 9]);
    g_wT[idx] = o;
}

// ---------------- prep: attn B (W fp16 duplicated halves) ----------------
__global__ __launch_bounds__(256) void prep_attnB_kernel(const float* __restrict__ attW)
{
    const int r = blockIdx.x;                 // e*512 + o
    const int tid = threadIdx.x;
    const float* src = attW + (size_t)r * H2;
    __half* dB = g_aB + (size_t)r * KPA;
    for (int col = tid; col < KPA; col += 256) {
        int kk = col & 511;
        dB[col] = __float2half_rn(src[kk]);
    }
}

// ---------------- prep: attn A (fp16 hi | lo of g_HS) ----------------
__global__ __launch_bounds__(256) void prep_attnA_kernel()
{
    const int r = blockIdx.x;                 // e*16384 + m
    const int tid = threadIdx.x;
    const float* src = g_HS + (size_t)r * H2;
    __half* dA = g_aA + (size_t)r * KPA;
    for (int col = tid; col < KPA; col += 256) {
        int kk = col & 511;
        float v = src[kk];
        __half hi = __float2half_rn(v);
        dA[col] = (col < 512) ? hi : __float2half_rn(v - __half2float(hi));
    }
}

// ---------------- proj GEMM (mma.sync fp16, K=640) ----------------
__global__ __launch_bounds__(256) void proj_mma_kernel(
    const float* __restrict__ bf, const float* __restrict__ bb)
{
    __shared__ __align__(16) uint32_t As[128][36];
    __shared__ __align__(16) uint32_t Bs[128][36];
    __shared__ float biasS[128];

    const int tid = threadIdx.x;
    const int warp = tid >> 5, lane = tid & 31;
    const int g = lane >> 2, tg = lane & 3;
    const int warp_m = (warp >> 2) * 64;
    const int warp_n = (warp & 3) * 32;

    const int n0 = blockIdx.x * 128;
    const int m0 = blockIdx.y * 128;
    const int b_i = blockIdx.y;
    const int c = n0 >> 10, e = c >> 1, d = c & 1;
    const int g0 = n0 & 1023;

    {
        const float* bias = (d ? bb : bf) + (size_t)e * G4;
        if (tid < 128) {
            int cg = g0 + tid;
            biasS[tid] = bias[(cg & 3) * 256 + (cg >> 2)];
        }
    }

    float acc[4][4][4];
#pragma unroll
    for (int m = 0; m < 4; m++)
#pragma unroll
        for (int n = 0; n < 4; n++)
#pragma unroll
            for (int q = 0; q < 4; q++) acc[m][n][q] = 0.0f;

    const uint4* Ag = (const uint4*)g_pA;     // 80 uint4 per row
    const uint4* Bg = (const uint4*)g_pB;

    for (int kc = 0; kc < 10; kc++) {
#pragma unroll
        for (int q = 0; q < 4; q++) {
            int idx = tid + q * 256;
            int r = idx >> 3, ju = idx & 7;
            *(uint4*)&As[r][ju * 4] = Ag[(size_t)(m0 + r) * 80 + kc * 8 + ju];
            *(uint4*)&Bs[r][ju * 4] = Bg[(size_t)(n0 + r) * 80 + kc * 8 + ju];
        }
        __syncthreads();
#pragma unroll
        for (int ks = 0; ks < 4; ks++) {
            uint32_t af[4][4], bfr[4][2];
#pragma unroll
            for (int m = 0; m < 4; m++) {
                int r0 = warp_m + m * 16 + g;
                af[m][0] = As[r0][ks * 8 + tg];
                af[m][1] = As[r0 + 8][ks * 8 + tg];
                af[m][2] = As[r0][ks * 8 + tg + 4];
                af[m][3] = As[r0 + 8][ks * 8 + tg + 4];
            }
#pragma unroll
            for (int n = 0; n < 4; n++) {
                int rn = warp_n + n * 8 + g;
                bfr[n][0] = Bs[rn][ks * 8 + tg];
                bfr[n][1] = Bs[rn][ks * 8 + tg + 4];
            }
#pragma unroll
            for (int m = 0; m < 4; m++)
#pragma unroll
                for (int n = 0; n < 4; n++) mma16816h(acc[m][n], af[m], bfr[n]);
        }
        __syncthreads();
    }

#pragma unroll
    for (int m = 0; m < 4; m++) {
        int l0 = warp_m + m * 16 + g;
        int l1 = l0 + 8;
        int t0 = d ? (Ldim - 1 - l0) : l0;
        int t1 = d ? (Ldim - 1 - l1) : l1;
        float* base0 = g_PROJ + (((size_t)c * Ldim + t0) * Bdim + b_i) * G4 + g0 + warp_n;
        float* base1 = g_PROJ + (((size_t)c * Ldim + t1) * Bdim + b_i) * G4 + g0 + warp_n;
#pragma unroll
        for (int n = 0; n < 4; n++) {
            int cc = n * 8 + 2 * tg;
            float2 v0 = { acc[m][n][0] + biasS[warp_n + cc],
                          acc[m][n][1] + biasS[warp_n + cc + 1] };
            float2 v1 = { acc[m][n][2] + biasS[warp_n + cc],
                          acc[m][n][3] + biasS[warp_n + cc + 1] };
            *(float2*)(base0 + cc) = v0;
            *(float2*)(base1 + cc) = v1;
        }
    }
}

// ---------------- LSTM recurrence: fp16 2-term, 512 threads, kt-pipelined ----------------
__global__ __launch_bounds__(512, 1) void lstm_batch_kernel()
{
    __shared__ uint32_t Hhi[16][132];
    __shared__ uint32_t Hlo[16][132];

    const int bid = blockIdx.x;
    const int c = bid >> 3, s = bid & 7;
    const int b0 = s * 16;
    const int e = c >> 1, d = c & 1;
    const int tid = threadIdx.x;
    const int warp = tid >> 5, lane = tid & 31;      // warp 0..15
    const int wOld = warp >> 1;
    const int ntB = (warp & 1) * 8;
    const int g = lane >> 2, tg = lane & 3;
    const bool evenp = (tg & 1) == 0;

    const uint2* Wlane = g_wT + ((size_t)c * 8 + wOld) * 256 * 32 + (ntB * 32 + lane);

    float cst[8];
#pragma unroll
    for (int i = 0; i < 8; i++) cst[i] = 0.0f;

    for (int t = 0; t < Ldim; t++) {
        float acc[8][4];
#pragma unroll
        for (int nt = 0; nt < 8; nt++)
#pragma unroll
            for (int q = 0; q < 4; q++) acc[nt][q] = 0.0f;

        if (t > 0) {
            uint2 bufA[8], bufB[8];
#pragma unroll
            for (int nt = 0; nt < 8; nt++) bufA[nt] = __ldcg(Wlane + nt * 32);

            for (int ktp = 0; ktp < 8; ktp++) {
                const int kt0 = 2 * ktp, kt1 = 2 * ktp + 1;
                {
                    const uint2* wr = Wlane + kt1 * 512;
#pragma unroll
                    for (int nt = 0; nt < 8; nt++) bufB[nt] = __ldcg(wr + nt * 32);
                }
                {
                    uint32_t ah[4], al[4];
                    ah[0] = Hhi[g][kt0 * 8 + tg];
                    ah[1] = Hhi[g + 8][kt0 * 8 + tg];
                    ah[2] = Hhi[g][kt0 * 8 + tg + 4];
                    ah[3] = Hhi[g + 8][kt0 * 8 + tg + 4];
                    al[0] = Hlo[g][kt0 * 8 + tg];
                    al[1] = Hlo[g + 8][kt0 * 8 + tg];
                    al[2] = Hlo[g][kt0 * 8 + tg + 4];
                    al[3] = Hlo[g + 8][kt0 * 8 + tg + 4];
#pragma unroll
                    for (int nt = 0; nt < 8; nt++) {
                        uint32_t bh[2] = { bufA[nt].x, bufA[nt].y };
                        mma16816h(acc[nt], ah, bh);
                        mma16816h(acc[nt], al, bh);
                    }
                }
                if (ktp < 7) {
                    const uint2* wr = Wlane + (kt0 + 2) * 512;
#pragma unroll
                    for (int nt = 0; nt < 8; nt++) bufA[nt] = __ldcg(wr + nt * 32);
                }
                {
                    uint32_t ah[4], al[4];
                    ah[0] = Hhi[g][kt1 * 8 + tg];
                    ah[1] = Hhi[g + 8][kt1 * 8 + tg];
                    ah[2] = Hhi[g][kt1 * 8 + tg + 4];
                    ah[3] = Hhi[g + 8][kt1 * 8 + tg + 4];
                    al[0] = Hlo[g][kt1 * 8 + tg];
                    al[1] = Hlo[g + 8][kt1 * 8 + tg];
                    al[2] = Hlo[g][kt1 * 8 + tg + 4];
                    al[3] = Hlo[g + 8][kt1 * 8 + tg + 4];
#pragma unroll
                    for (int nt = 0; nt < 8; nt++) {
                        uint32_t bh[2] = { bufB[nt].x, bufB[nt].y };
                        mma16816h(acc[nt], ah, bh);
                        mma16816h(acc[nt], al, bh);
                    }
                }
            }
        }
        __syncthreads();

        const int lo_t = d ? (Ldim - 1 - t) : t;
        const float* projb = g_PROJ + (((size_t)c * Ldim + t) * Bdim + b0) * G4;
        const int row = g + (evenp ? 0 : 8);
#pragma unroll
        for (int nt = 0; nt < 8; nt++) {
            int ntg = ntB + nt;
            float a0 = acc[nt][0], a1 = acc[nt][1];
            float a2 = acc[nt][2], a3 = acc[nt][3];
            float t0 = __shfl_xor_sync(0xFFFFFFFFu, a0, 1);
            float t1 = __shfl_xor_sync(0xFFFFFFFFu, a1, 1);
            float t2 = __shfl_xor_sync(0xFFFFFFFFu, a2, 1);
            float t3 = __shfl_xor_sync(0xFFFFFFFFu, a3, 1);
            int hd = wOld * 32 + ntg * 2 + (tg >> 1);
            float4 pj = *(const float4*)(projb + (size_t)row * G4 + hd * 4);
            float gi = (evenp ? a0 : t2) + pj.x;
            float gf = (evenp ? a1 : t3) + pj.y;
            float gg = (evenp ? t0 : a2) + pj.z;
            float go = (evenp ? t1 : a3) + pj.w;
            float cn = sigf(gf) * cst[nt] + sigf(gi) * tanh_fast(gg);
            cst[nt] = cn;
            float h = sigf(go) * tanh_fast(cn);
            g_HS[(((size_t)e * Bdim + (b0 + row)) * Ldim + lo_t) * H2 + d * Hdim + hd] = h;
            float hB = __shfl_xor_sync(0xFFFFFFFFu, h, 2);
            if ((tg >> 1) == 0) {
                __half ha = __float2half_rn(h);
                __half hb = __float2half_rn(hB);
                float hA_hi = __half2float(ha);
                float hB_hi = __half2float(hb);
                Hhi[row][wOld * 16 + ntg] = pack_h2(h, hB);
                Hlo[row][wOld * 16 + ntg] = pack_h2(h - hA_hi, hB - hB_hi);
            }
        }
        __syncthreads();
    }
}

// ---------------- attention logits GEMM (mma.sync fp16, K=1024) ----------------
__global__ __launch_bounds__(256) void attn_mma_kernel(
    const float* __restrict__ attb, const float* __restrict__ attv)
{
    __shared__ __align__(16) uint32_t As[128][36];
    __shared__ __align__(16) uint32_t Bs[128][36];
    __shared__ float red[128][17];

    const int tid = threadIdx.x;
    const int warp = tid >> 5, lane = tid & 31;
    const int g = lane >> 2, tg = lane & 3;
    const int warp_m = (warp >> 2) * 64;
    const int warp_n = (warp & 3) * 32;

    const int m0 = blockIdx.x * 128;
    const int e = blockIdx.y;

    const uint4* Ag = (const uint4*)g_aA;     // 128 uint4 per row
    const uint4* Bg = (const uint4*)g_aB;     // 128 uint4 per row
    const float* abp = attb + (size_t)e * H2;
    const float* avp = attv + (size_t)e * H2;

    float part[4][2];
#pragma unroll
    for (int m = 0; m < 4; m++) { part[m][0] = 0.0f; part[m][1] = 0.0f; }

    for (int nc = 0; nc < 4; nc++) {
        const int n0 = nc * 128;
        float acc[4][4][4];
#pragma unroll
        for (int m = 0; m < 4; m++)
#pragma unroll
            for (int n = 0; n < 4; n++)
#pragma unroll
                for (int q = 0; q < 4; q++) acc[m][n][q] = 0.0f;

        for (int kc = 0; kc < 16; kc++) {
#pragma unroll
            for (int q = 0; q < 4; q++) {
                int idx = tid + q * 256;
                int r = idx >> 3, ju = idx & 7;
                *(uint4*)&As[r][ju * 4] =
                    Ag[((size_t)e * 16384 + m0 + r) * 128 + kc * 8 + ju];
                *(uint4*)&Bs[r][ju * 4] =
                    Bg[((size_t)e * H2 + n0 + r) * 128 + kc * 8 + ju];
            }
            __syncthreads();
#pragma unroll
            for (int ks = 0; ks < 4; ks++) {
                uint32_t af[4][4], bfr[4][2];
#pragma unroll
                for (int m = 0; m < 4; m++) {
                    int r0 = warp_m + m * 16 + g;
                    af[m][0] = As[r0][ks * 8 + tg];
                    af[m][1] = As[r0 + 8][ks * 8 + tg];
                    af[m][2] = As[r0][ks * 8 + tg + 4];
                    af[m][3] = As[r0 + 8][ks * 8 + tg + 4];
                }
#pragma unroll
                for (int n = 0; n < 4; n++) {
                    int rn = warp_n + n * 8 + g;
                    bfr[n][0] = Bs[rn][ks * 8 + tg];
                    bfr[n][1] = Bs[rn][ks * 8 + tg + 4];
                }
#pragma unroll
                for (int m = 0; m < 4; m++)
#pragma unroll
                    for (int n = 0; n < 4; n++) mma16816h(acc[m][n], af[m], bfr[n]);
            }
            __syncthreads();
        }

#pragma unroll
        for (int n = 0; n < 4; n++) {
            int o = n0 + warp_n + n * 8 + 2 * tg;
            float ab0 = abp[o], ab1 = abp[o + 1];
            float av0 = avp[o], av1 = avp[o + 1];
#pragma unroll
            for (int m = 0; m < 4; m++) {
                part[m][0] += tanh_fast(acc[m][n][0] + ab0) * av0
                            + tanh_fast(acc[m][n][1] + ab1) * av1;
                part[m][1] += tanh_fast(acc[m][n][2] + ab0) * av0
                            + tanh_fast(acc[m][n][3] + ab1) * av1;
            }
        }
    }

#pragma unroll
    for (int m = 0; m < 4; m++) {
        int r0 = warp_m + m * 16 + g;
        red[r0][(warp & 3) * 4 + tg] = part[m][0];
        red[r0 + 8][(warp & 3) * 4 + tg] = part[m][1];
    }
    __syncthreads();
    if (tid < 128) {
        float ss = 0.0f;
#pragma unroll
        for (int q = 0; q < 16; q++) ss += red[tid][q];
        g_s[(size_t)e * Bdim * Ldim + m0 + tid] = ss;
    }
}

// ---------------- softmax over L + weighted pooling ----------------
__global__ __launch_bounds__(128) void softmax_pool_kernel()
{
    const int e = blockIdx.y, b = blockIdx.x;
    __shared__ float wts[Ldim];
    __shared__ float red[128];
    const int tid = threadIdx.x;

    float v = g_s[((size_t)e * Bdim + b) * Ldim + tid];
    red[tid] = v; __syncthreads();
    for (int st = 64; st > 0; st >>= 1) {
        if (tid < st) red[tid] = fmaxf(red[tid], red[tid + st]);
        __syncthreads();
    }
    float mx = red[0]; __syncthreads();
    float ev = expf(v - mx);
    red[tid] = ev; __syncthreads();
    for (int st = 64; st > 0; st >>= 1) {
        if (tid < st) red[tid] += red[tid + st];
        __syncthreads();
    }
    float inv = 1.0f / red[0];
    wts[tid] = ev * inv;
    __syncthreads();

    const float* hrow = g_HS + ((size_t)e * Bdim + b) * Ldim * H2;
    float accv[4] = {0.f, 0.f, 0.f, 0.f};
    for (int l = 0; l < Ldim; l++) {
        float a = wts[l];
        const float* hp = hrow + (size_t)l * H2;
#pragma unroll
        for (int j = 0; j < 4; j++) accv[j] += a * hp[tid + j * 128];
    }
    float* op = g_OUT + ((size_t)e * Bdim + b) * H2;
#pragma unroll
    for (int j = 0; j < 4; j++) op[tid + j * 128] = accv[j];
}

// ---------------- output copy + final FC ----------------
__global__ void copy_out_kernel(float* __restrict__ out)
{
    int i = blockIdx.x * blockDim.x + threadIdx.x;
    if (i < NEx * Bdim * H2) out[256 + i] = g_OUT[i];
}

__global__ __launch_bounds__(128) void final_kernel(
    const int* __restrict__ z, const float* __restrict__ fcW,
    const float* __restrict__ fcb, float* __restrict__ out)
{
    const int b = blockIdx.x;
    const int tid = threadIdx.x;
    const int zi = z[b];
    const float* sel = g_OUT + ((size_t)(1 + zi) * Bdim + b) * H2;
    const float* gen = g_OUT + (size_t)b * H2;
    __shared__ float red0[128], red1[128];
    float a0 = 0.f, a1 = 0.f;
    for (int dd = tid; dd < 1024; dd += 128) {
        float cv = (dd < 512) ? sel[dd] : gen[dd - 512];
        a0 += cv * fcW[dd];
        a1 += cv * fcW[1024 + dd];
    }
    red0[tid] = a0; red1[tid] = a1; __syncthreads();
    for (int st = 64; st > 0; st >>= 1) {
        if (tid < st) { red0[tid] += red0[tid + st]; red1[tid] += red1[tid + st]; }
        __syncthreads();
    }
    if (tid == 0) {
        out[b * 2 + 0] = red0[0] + fcb[0];
        out[b * 2 + 1] = red1[0] + fcb[1];
    }
}

// ---------------- launch ----------------
extern "C" void kernel_launch(void* const* d_in, const int* in_sizes, int n_in,
                              void* d_out, int out_size)
{
    (void)in_sizes; (void)n_in; (void)out_size;
    const float* x     = (const float*)d_in[0];
    const int*   z     = (const int*)  d_in[1];
    const float* wih_f = (const float*)d_in[2];
    const float* whh_f = (const float*)d_in[3];
    const float* b_f   = (const float*)d_in[4];
    const float* wih_b = (const float*)d_in[5];
    const float* whh_b = (const float*)d_in[6];
    const float* b_b   = (const float*)d_in[7];
    const float* attW  = (const float*)d_in[8];
    const float* attb  = (const float*)d_in[9];
    const float* attv  = (const float*)d_in[10];
    const float* fcW   = (const float*)d_in[11];
    const float* fcb   = (const float*)d_in[12];
    float* out = (float*)d_out;

    prep_proj_kernel<<<16384 + 10240, 256>>>(x, wih_f, wih_b);
    prep_wT_kernel<<<2560, 256>>>(whh_f, whh_b);
    prep_attnB_kernel<<<NEx * H2, 256>>>(attW);
    proj_mma_kernel<<<dim3(80, 128), 256>>>(b_f, b_b);
    lstm_batch_kernel<<<80, 512>>>();
    prep_attnA_kernel<<<NEx * 16384, 256>>>();
    attn_mma_kernel<<<dim3(128, 5), 256>>>(attb, attv);
    softmax_pool_kernel<<<dim3(128, 5), 128>>>();
    copy_out_kernel<<<(NEx * Bdim * H2 + 255) / 256, 256>>>(out);
    final_kernel<<<128, 128>>>(z, fcW, fcb, out);
}